// round 3
// baseline (speedup 1.0000x reference)
#include <cuda_runtime.h>
#include <math.h>

// ---------------- problem constants ----------------
#define DEPTH  2
#define NBATCH 4
#define SEQ    8192
#define DIMM   512
#define HEADS  8
#define DHEAD  64
#define NBF    256          // random features m
#define FFD    2048
#define TOK    (NBATCH*SEQ) // 32768
#define BH     (NBATCH*HEADS) // 32

#define NORMALIZER 0.3535533905932738f   // 64^-0.25
#define RATIO      0.0625f               // 256^-0.5
#define PHI_EPS    1e-4f
#define LN_EPS     1e-5f

// ---------------- device scratch (allocation-free) ----------------
// One consolidated arena. Layout (in floats), TD = TOK*DIMM = 16,777,216:
//   y  : [0      , TD)
//   q  : [TD     , 2TD)      \
//   k  : [2TD    , 3TD)       | attention phase
//   v  : [3TD    , 4TD)       |
//   o  : [4TD    , 5TD)      /
//   h  : [TD     , 5TD)      -- FF phase, aliases q..o (dead by then)
//   qp : [5TD    , 9TD)      (BH*SEQ*NBF = 4TD)
//   kp : [9TD    , 13TD)
#define TD ((size_t)TOK*DIMM)
__device__ float g_arena[13*TD];
__device__ float g_projT[DHEAD*NBF];
__device__ float g_ksum[BH*NBF];
__device__ int   g_kmax[BH];
__device__ float g_ctx[BH*NBF*DHEAD];
__device__ float g_dinv[BH*SEQ];

// ---------------- helpers ----------------
__device__ __forceinline__ float warpSum(float v){
    #pragma unroll
    for (int o=16;o;o>>=1) v += __shfl_xor_sync(0xffffffffu, v, o);
    return v;
}
__device__ __forceinline__ float warpMax(float v){
    #pragma unroll
    for (int o=16;o;o>>=1) v = fmaxf(v, __shfl_xor_sync(0xffffffffu, v, o));
    return v;
}
__device__ __forceinline__ int   f2ord(float f){ int i=__float_as_int(f); return i ^ ((i>>31) & 0x7fffffff); }
__device__ __forceinline__ float ord2f(int i){ return __int_as_float(i ^ ((i>>31) & 0x7fffffff)); }

// ---------------- layernorm: one block per token ----------------
__global__ void ln_kernel(const float* __restrict__ x, const float* __restrict__ g,
                          const float* __restrict__ b, float* __restrict__ y)
{
    int t = blockIdx.x;
    int tid = threadIdx.x;              // 128 threads, 4 floats each
    const float4* xr = (const float4*)(x + (size_t)t*DIMM);
    float4 v = xr[tid];
    __shared__ float wred[4];
    __shared__ float stats[2];
    int lane = tid & 31, w = tid >> 5;

    float s = v.x+v.y+v.z+v.w;
    s = warpSum(s);
    if (lane==0) wred[w]=s;
    __syncthreads();
    if (tid==0) stats[0] = (wred[0]+wred[1]+wred[2]+wred[3]) * (1.0f/DIMM);
    __syncthreads();
    float mean = stats[0];

    float dx0=v.x-mean, dx1=v.y-mean, dx2=v.z-mean, dx3=v.w-mean;
    float s2 = dx0*dx0+dx1*dx1+dx2*dx2+dx3*dx3;
    s2 = warpSum(s2);
    if (lane==0) wred[w]=s2;
    __syncthreads();
    if (tid==0) stats[1] = (wred[0]+wred[1]+wred[2]+wred[3]) * (1.0f/DIMM);
    __syncthreads();
    float inv = rsqrtf(stats[1] + LN_EPS);

    float4 gv = ((const float4*)g)[tid];
    float4 bv = ((const float4*)b)[tid];
    float4 out;
    out.x = dx0*inv*gv.x + bv.x;
    out.y = dx1*inv*gv.y + bv.y;
    out.z = dx2*inv*gv.z + bv.z;
    out.w = dx3*inv*gv.w + bv.w;
    ((float4*)(y + (size_t)t*DIMM))[tid] = out;
}

// ---------------- generic 128x128x8 SGEMM with register prefetch ----------------
// C = epi( alpha*(A*B + bias) ) [+ R]
// EPI: 0 = bias only, 1 = bias + residual, 2 = gelu(bias)
// batched: bz -> A + (bz/Hn)*strideAb + (bz%Hn)*strideAh ; C + bz*strideC ; B shared.
template<int EPI>
__global__ void __launch_bounds__(256, 2)
sgemm_kernel(const float* __restrict__ A, const float* __restrict__ Bm,
             const float* __restrict__ bias, const float* __restrict__ R,
             float* __restrict__ C,
             int K, int lda, int ldb, int ldc, int ldr,
             long strideAb, long strideAh, int Hn, long strideC, float alpha)
{
    int bz = blockIdx.z;
    const float* Ab = A + (long)(bz / Hn)*strideAb + (long)(bz % Hn)*strideAh;
    float* Cb = C + (long)bz*strideC;
    int row0 = blockIdx.x*128, col0 = blockIdx.y*128;

    __shared__ float As[8][128];
    __shared__ float Bs[8][128];

    int tid = threadIdx.x;
    int arow = tid >> 1, acol4 = (tid & 1)*4;
    int brow = tid >> 5, bcol4 = (tid & 31)*4;
    int ty = tid >> 4, tx = tid & 15;

    const float* aptr = Ab + (long)(row0+arow)*lda + acol4;
    const float* bptr = Bm + (long)brow*ldb + col0 + bcol4;

    float acc[8][8];
    #pragma unroll
    for (int i=0;i<8;i++)
        #pragma unroll
        for (int j=0;j<8;j++) acc[i][j]=0.f;

    // prefetch first tile
    float4 av = *(const float4*)(aptr);
    float4 bv = *(const float4*)(bptr);

    for (int k0=0; k0<K; k0+=8){
        As[acol4+0][arow]=av.x; As[acol4+1][arow]=av.y;
        As[acol4+2][arow]=av.z; As[acol4+3][arow]=av.w;
        *(float4*)(&Bs[brow][bcol4]) = bv;
        __syncthreads();

        if (k0+8 < K){   // issue next-tile loads early; consumed next iteration
            av = *(const float4*)(aptr + k0 + 8);
            bv = *(const float4*)(bptr + (long)(k0+8)*ldb);
        }

        #pragma unroll
        for (int kk=0;kk<8;kk++){
            float a[8], bb[8];
            #pragma unroll
            for (int i=0;i<8;i++) a[i]  = As[kk][ty*8+i];
            #pragma unroll
            for (int j=0;j<8;j++) bb[j] = Bs[kk][tx*8+j];
            #pragma unroll
            for (int i=0;i<8;i++)
                #pragma unroll
                for (int j=0;j<8;j++) acc[i][j] = fmaf(a[i], bb[j], acc[i][j]);
        }
        __syncthreads();
    }

    #pragma unroll
    for (int i=0;i<8;i++){
        int r = row0 + ty*8 + i;
        #pragma unroll
        for (int j=0;j<8;j++){
            int c = col0 + tx*8 + j;
            float v = acc[i][j];
            if (bias) v += bias[c];
            v *= alpha;
            if (EPI==2) v = 0.5f*v*(1.0f + erff(v*0.70710678118654752f));
            if (EPI==1) v += R[(long)r*ldr + c];
            Cb[(long)r*ldc + c] = v;
        }
    }
}

// ---------------- proj transpose: [256,64] -> [64,256] ----------------
__global__ void transpose_proj(const float* __restrict__ proj, float* __restrict__ pt)
{
    int idx = blockIdx.x*256 + threadIdx.x;   // over 16384
    if (idx < NBF*DHEAD){
        int m = idx >> 6, k = idx & 63;
        pt[k*NBF + m] = proj[idx];
    }
}

// ---------------- zero / init per layer ----------------
__global__ void init_kernel()
{
    int idx = blockIdx.x*256 + threadIdx.x;
    if (idx < BH*NBF*DHEAD) g_ctx[idx] = 0.f;
    if (idx < BH*NBF)       g_ksum[idx] = 0.f;
    if (idx < BH)           g_kmax[idx] = f2ord(-INFINITY);
}

// ---------------- global max of kdash per (b,h) ----------------
__global__ void kmax_kernel(const float* __restrict__ kp)
{
    int bh = blockIdx.y;
    const float* p = kp + (size_t)bh*SEQ*NBF + (size_t)blockIdx.x*32768;
    int tid = threadIdx.x;
    float m = -INFINITY;
    for (int i=tid; i<32768; i+=256) m = fmaxf(m, p[i]);
    __shared__ float wred[8];
    int lane = tid & 31, w = tid >> 5;
    m = warpMax(m);
    if (lane==0) wred[w]=m;
    __syncthreads();
    if (tid==0){
        float t = -INFINITY;
        #pragma unroll
        for (int i=0;i<8;i++) t = fmaxf(t, wred[i]);
        atomicMax(&g_kmax[bh], f2ord(t));
    }
}

// ---------------- phi finish: dash -> ratio*(exp(dash - diag - max)+eps) ----------------
// qk = scaled q/k in [T,512] layout ; dash = in/out [bh][n][m]
template<bool QMODE>
__global__ void phi_finish(const float* __restrict__ qk, float* __restrict__ dash)
{
    int bh = blockIdx.y, n = blockIdx.x;
    int b = bh >> 3, h = bh & 7;
    int tid = threadIdx.x;     // 256 = NBF
    float* row = dash + ((size_t)bh*SEQ + n)*NBF;
    float dv = row[tid];
    const float* qrow = qk + ((size_t)(b*SEQ + n))*DIMM + h*DHEAD;
    float q2 = (tid < DHEAD) ? qrow[tid]*qrow[tid] : 0.f;

    __shared__ float wred[8];
    __shared__ float res[2];
    int lane = tid & 31, w = tid >> 5;

    float s = warpSum(q2);
    if (lane==0) wred[w]=s;
    __syncthreads();
    if (tid==0){
        float t=0.f;
        #pragma unroll
        for (int i=0;i<8;i++) t += wred[i];
        res[0]=t;
    }
    __syncthreads();

    float mx;
    if (QMODE){
        float m = warpMax(dv);
        if (lane==0) wred[w]=m;
        __syncthreads();
        if (tid==0){
            float t=-INFINITY;
            #pragma unroll
            for (int i=0;i<8;i++) t = fmaxf(t, wred[i]);
            res[1]=t;
        }
        __syncthreads();
        mx = res[1];
    } else {
        mx = ord2f(g_kmax[bh]);
    }
    float diag = 0.5f*res[0];
    row[tid] = RATIO*(expf(dv - diag - mx) + PHI_EPS);
}

// ---------------- k_sum[bh][m] = sum_n kp ----------------
__global__ void ksum_kernel(const float* __restrict__ kp)
{
    int bh = blockIdx.y;
    int n0 = blockIdx.x*(SEQ/32);
    int tid = threadIdx.x;  // 256 = NBF
    const float* base = kp + ((size_t)bh*SEQ + n0)*NBF + tid;
    float s = 0.f;
    #pragma unroll 4
    for (int r=0; r<SEQ/32; r++) s += base[(size_t)r*NBF];
    atomicAdd(&g_ksum[bh*NBF + tid], s);
}

// ---------------- ctx[bh][m][d] = sum_n kp[bh][n][m]*v[b][n][h][d] (split-K + atomics) ----------------
__global__ void __launch_bounds__(256)
ctx_kernel(const float* __restrict__ kp, const float* __restrict__ v)
{
    int bh = blockIdx.z; int b = bh >> 3, h = bh & 7;
    const float* kpb = kp + (size_t)bh*SEQ*NBF;
    const float* vb  = v  + (size_t)b*SEQ*DIMM + h*DHEAD;
    int m0 = blockIdx.x*64;
    int n0 = blockIdx.y*(SEQ/8);  // 1024 per split

    __shared__ float Ks[16][64];
    __shared__ float Vs[16][64];
    int tid = threadIdx.x;
    int ty = tid >> 4, tx = tid & 15;
    int lr = tid >> 4, lc4 = (tid & 15)*4;

    float acc[4][4];
    #pragma unroll
    for (int i=0;i<4;i++)
        #pragma unroll
        for (int j=0;j<4;j++) acc[i][j]=0.f;

    for (int n=n0; n<n0+SEQ/8; n+=16){
        __syncthreads();
        *(float4*)(&Ks[lr][lc4]) = *(const float4*)(kpb + (size_t)(n+lr)*NBF + m0 + lc4);
        *(float4*)(&Vs[lr][lc4]) = *(const float4*)(vb  + (size_t)(n+lr)*DIMM + lc4);
        __syncthreads();
        #pragma unroll
        for (int kk=0;kk<16;kk++){
            float a[4], bb[4];
            #pragma unroll
            for (int i=0;i<4;i++) a[i]  = Ks[kk][ty*4+i];
            #pragma unroll
            for (int j=0;j<4;j++) bb[j] = Vs[kk][tx*4+j];
            #pragma unroll
            for (int i=0;i<4;i++)
                #pragma unroll
                for (int j=0;j<4;j++) acc[i][j] = fmaf(a[i], bb[j], acc[i][j]);
        }
    }
    #pragma unroll
    for (int i=0;i<4;i++)
        #pragma unroll
        for (int j=0;j<4;j++)
            atomicAdd(&g_ctx[((size_t)bh*NBF + m0 + ty*4 + i)*DHEAD + tx*4 + j], acc[i][j]);
}

// ---------------- d_inv[bh][n] = 1 / (qp[n,:] . k_sum) ----------------
__global__ void dinv_kernel(const float* __restrict__ qp)
{
    int bh = blockIdx.y;
    int n = blockIdx.x*8 + (threadIdx.x >> 5);
    int lane = threadIdx.x & 31;
    const float* row = qp + ((size_t)bh*SEQ + n)*NBF;
    const float* ks  = g_ksum + bh*NBF;
    float s = 0.f;
    #pragma unroll 2
    for (int j=lane; j<NBF; j+=32) s += row[j]*ks[j];
    s = warpSum(s);
    if (lane==0) g_dinv[(size_t)bh*SEQ + n] = 1.0f/s;
}

// ---------------- o = dinv * (qp @ ctx), scattered into [T, 512] ----------------
__global__ void __launch_bounds__(256, 2)
ogemm_kernel(const float* __restrict__ qp, float* __restrict__ o)
{
    int bh = blockIdx.z; int b = bh >> 3, h = bh & 7;
    const float* A  = qp    + (size_t)bh*SEQ*NBF;
    const float* Bm = g_ctx + (size_t)bh*NBF*DHEAD;
    int row0 = blockIdx.x*128;

    __shared__ float As[8][128];
    __shared__ float Bs[8][64];
    int tid = threadIdx.x;
    int ty = tid >> 4, tx = tid & 15;

    float acc[8][4];
    #pragma unroll
    for (int i=0;i<8;i++)
        #pragma unroll
        for (int j=0;j<4;j++) acc[i][j]=0.f;

    for (int k0=0; k0<NBF; k0+=8){
        float4 av = *(const float4*)(A + (size_t)(row0 + (tid>>1))*NBF + k0 + (tid&1)*4);
        __syncthreads();
        {
            int arow = tid >> 1, acol4 = (tid & 1)*4;
            As[acol4+0][arow]=av.x; As[acol4+1][arow]=av.y;
            As[acol4+2][arow]=av.z; As[acol4+3][arow]=av.w;
        }
        if (tid < 128)
            *(float4*)(&Bs[tid>>4][(tid&15)*4]) =
                *(const float4*)(Bm + (size_t)(k0 + (tid>>4))*DHEAD + (tid&15)*4);
        __syncthreads();
        #pragma unroll
        for (int kk=0;kk<8;kk++){
            float a[8], bb[4];
            #pragma unroll
            for (int i=0;i<8;i++) a[i]  = As[kk][ty*8+i];
            #pragma unroll
            for (int j=0;j<4;j++) bb[j] = Bs[kk][tx*4+j];
            #pragma unroll
            for (int i=0;i<8;i++)
                #pragma unroll
                for (int j=0;j<4;j++) acc[i][j] = fmaf(a[i], bb[j], acc[i][j]);
        }
    }
    #pragma unroll
    for (int i=0;i<8;i++){
        int n = row0 + ty*8 + i;
        float di = g_dinv[(size_t)bh*SEQ + n];
        #pragma unroll
        for (int j=0;j<4;j++)
            o[((size_t)(b*SEQ + n))*DIMM + h*DHEAD + tx*4 + j] = acc[i][j]*di;
    }
}

// ---------------- host driver ----------------
extern "C" void kernel_launch(void* const* d_in, const int* in_sizes, int n_in,
                              void* d_out, int out_size)
{
    const float* ln1_g = (const float*)d_in[1];
    const float* ln1_b = (const float*)d_in[2];
    const float* ln2_g = (const float*)d_in[3];
    const float* ln2_b = (const float*)d_in[4];
    const float* Wq    = (const float*)d_in[5];
    const float* bq    = (const float*)d_in[6];
    const float* Wk    = (const float*)d_in[7];
    const float* bk    = (const float*)d_in[8];
    const float* Wv    = (const float*)d_in[9];
    const float* bv    = (const float*)d_in[10];
    const float* Wo    = (const float*)d_in[11];
    const float* bo    = (const float*)d_in[12];
    const float* proj  = (const float*)d_in[13];
    const float* W1    = (const float*)d_in[14];
    const float* b1    = (const float*)d_in[15];
    const float* W2    = (const float*)d_in[16];
    const float* b2    = (const float*)d_in[17];

    float* x = (float*)d_out;
    cudaMemcpyAsync(x, d_in[0], TD*sizeof(float), cudaMemcpyDeviceToDevice);

    float* arena;
    cudaGetSymbolAddress((void**)&arena, g_arena);
    float* py  = arena;            // TD
    float* pq  = arena + TD;       // TD
    float* pk  = arena + 2*TD;     // TD
    float* pv  = arena + 3*TD;     // TD
    float* po  = arena + 4*TD;     // TD
    float* ph  = arena + TD;       // 4*TD, aliases q..o (FF phase only)
    float* pqp = arena + 5*TD;     // 4*TD
    float* pkp = arena + 9*TD;     // 4*TD
    float* pprojT;
    cudaGetSymbolAddress((void**)&pprojT, g_projT);

    for (int i=0; i<DEPTH; i++){
        // ---- attention block ----
        ln_kernel<<<TOK,128>>>(x, ln1_g + i*DIMM, ln1_b + i*DIMM, py);

        dim3 gQKV(TOK/128, DIMM/128, 1);
        sgemm_kernel<0><<<gQKV,256>>>(py, Wq + (size_t)i*DIMM*DIMM, bq + i*DIMM, nullptr, pq,
                                      DIMM, DIMM, DIMM, DIMM, 0, 0, 0, 1, 0, NORMALIZER);
        sgemm_kernel<0><<<gQKV,256>>>(py, Wk + (size_t)i*DIMM*DIMM, bk + i*DIMM, nullptr, pk,
                                      DIMM, DIMM, DIMM, DIMM, 0, 0, 0, 1, 0, NORMALIZER);
        sgemm_kernel<0><<<gQKV,256>>>(py, Wv + (size_t)i*DIMM*DIMM, bv + i*DIMM, nullptr, pv,
                                      DIMM, DIMM, DIMM, DIMM, 0, 0, 0, 1, 0, 1.0f);

        transpose_proj<<<64,256>>>(proj + (size_t)i*NBF*DHEAD, pprojT);

        // kdash = k_head @ projT  (batched over (b,h))
        dim3 gDASH(SEQ/128, NBF/128, BH);
        sgemm_kernel<0><<<gDASH,256>>>(pk, pprojT, nullptr, nullptr, pkp,
                                       DHEAD, DIMM, NBF, NBF, 0,
                                       (long)SEQ*DIMM, DHEAD, HEADS, (long)SEQ*NBF, 1.0f);
        init_kernel<<<2048,256>>>();
        kmax_kernel<<<dim3(64,BH),256>>>(pkp);
        phi_finish<false><<<dim3(SEQ,BH),256>>>(pk, pkp);
        ksum_kernel<<<dim3(32,BH),256>>>(pkp);

        // qdash = q_head @ projT, then per-row finish
        sgemm_kernel<0><<<gDASH,256>>>(pq, pprojT, nullptr, nullptr, pqp,
                                       DHEAD, DIMM, NBF, NBF, 0,
                                       (long)SEQ*DIMM, DHEAD, HEADS, (long)SEQ*NBF, 1.0f);
        phi_finish<true><<<dim3(SEQ,BH),256>>>(pq, pqp);

        ctx_kernel<<<dim3(NBF/64, 8, BH),256>>>(pkp, pv);
        dinv_kernel<<<dim3(SEQ/8, BH),256>>>(pqp);
        ogemm_kernel<<<dim3(SEQ/128, 1, BH),256>>>(pqp, po);

        // x += o @ Wo + bo
        sgemm_kernel<1><<<gQKV,256>>>(po, Wo + (size_t)i*DIMM*DIMM, bo + i*DIMM, x, x,
                                      DIMM, DIMM, DIMM, DIMM, DIMM, 0, 0, 1, 0, 1.0f);

        // ---- feed-forward block ----
        ln_kernel<<<TOK,128>>>(x, ln2_g + i*DIMM, ln2_b + i*DIMM, py);

        dim3 gW1(TOK/128, FFD/128, 1);
        sgemm_kernel<2><<<gW1,256>>>(py, W1 + (size_t)i*DIMM*FFD, b1 + i*FFD, nullptr, ph,
                                     DIMM, DIMM, FFD, FFD, 0, 0, 0, 1, 0, 1.0f);
        dim3 gW2(TOK/128, DIMM/128, 1);
        sgemm_kernel<1><<<gW2,256>>>(ph, W2 + (size_t)i*FFD*DIMM, b2 + i*DIMM, x, x,
                                     FFD, FFD, DIMM, DIMM, DIMM, 0, 0, 1, 0, 1.0f);
    }
}

// round 5
// speedup vs baseline: 1.6552x; 1.6552x over previous
#include <cuda_runtime.h>
#include <math.h>

// ---------------- problem constants ----------------
#define DEPTH  2
#define NBATCH 4
#define SEQ    8192
#define DIMM   512
#define HEADS  8
#define DHEAD  64
#define NBF    256          // random features m
#define FFD    2048
#define TOK    (NBATCH*SEQ) // 32768
#define BH     (NBATCH*HEADS) // 32

#define NORMALIZER 0.3535533905932738f   // 64^-0.25
#define RATIO      0.0625f               // 256^-0.5
#define PHI_EPS    1e-4f
#define LN_EPS     1e-5f
#define RSQRT2     0.70710678118654752f

// ---------------- device scratch (allocation-free) ----------------
#define TD ((size_t)TOK*DIMM)
__device__ float g_arena[13*TD];
__device__ float g_projT[DHEAD*NBF];
__device__ float g_ksum[BH*NBF];
__device__ int   g_kmax[BH];
__device__ float g_ctx[BH*NBF*DHEAD];
__device__ float g_dinv[BH*SEQ];

// ---------------- helpers ----------------
__device__ __forceinline__ float warpSum(float v){
    #pragma unroll
    for (int o=16;o;o>>=1) v += __shfl_xor_sync(0xffffffffu, v, o);
    return v;
}
__device__ __forceinline__ float warpMax(float v){
    #pragma unroll
    for (int o=16;o;o>>=1) v = fmaxf(v, __shfl_xor_sync(0xffffffffu, v, o));
    return v;
}
__device__ __forceinline__ int   f2ord(float f){ int i=__float_as_int(f); return i ^ ((i>>31) & 0x7fffffff); }
__device__ __forceinline__ float ord2f(int i){ return __int_as_float(i ^ ((i>>31) & 0x7fffffff)); }

__device__ __forceinline__ float tf32r(float x){
    unsigned u;
    asm("cvt.rna.tf32.f32 %0, %1;" : "=r"(u) : "f"(x));
    return __uint_as_float(u);
}

__device__ __forceinline__ void mma8(float* d, const float* a, const float* b){
    asm volatile(
      "mma.sync.aligned.m16n8k8.row.col.f32.tf32.tf32.f32 "
      "{%0,%1,%2,%3},{%4,%5,%6,%7},{%8,%9},{%0,%1,%2,%3};"
      : "+f"(d[0]),"+f"(d[1]),"+f"(d[2]),"+f"(d[3])
      : "r"(__float_as_uint(a[0])),"r"(__float_as_uint(a[1])),
        "r"(__float_as_uint(a[2])),"r"(__float_as_uint(a[3])),
        "r"(__float_as_uint(b[0])),"r"(__float_as_uint(b[1])));
}

// ---------------- layernorm: one block per token ----------------
__global__ void ln_kernel(const float* __restrict__ x, const float* __restrict__ g,
                          const float* __restrict__ b, float* __restrict__ y)
{
    int t = blockIdx.x;
    int tid = threadIdx.x;              // 128 threads, 4 floats each
    const float4* xr = (const float4*)(x + (size_t)t*DIMM);
    float4 v = xr[tid];
    __shared__ float wred[4];
    __shared__ float stats[2];
    int lane = tid & 31, w = tid >> 5;

    float s = v.x+v.y+v.z+v.w;
    s = warpSum(s);
    if (lane==0) wred[w]=s;
    __syncthreads();
    if (tid==0) stats[0] = (wred[0]+wred[1]+wred[2]+wred[3]) * (1.0f/DIMM);
    __syncthreads();
    float mean = stats[0];

    float dx0=v.x-mean, dx1=v.y-mean, dx2=v.z-mean, dx3=v.w-mean;
    float s2 = dx0*dx0+dx1*dx1+dx2*dx2+dx3*dx3;
    s2 = warpSum(s2);
    if (lane==0) wred[w]=s2;
    __syncthreads();
    if (tid==0) stats[1] = (wred[0]+wred[1]+wred[2]+wred[3]) * (1.0f/DIMM);
    __syncthreads();
    float inv = rsqrtf(stats[1] + LN_EPS);

    float4 gv = ((const float4*)g)[tid];
    float4 bv = ((const float4*)b)[tid];
    float4 out;
    out.x = dx0*inv*gv.x + bv.x;
    out.y = dx1*inv*gv.y + bv.y;
    out.z = dx2*inv*gv.z + bv.z;
    out.w = dx3*inv*gv.w + bv.w;
    ((float4*)(y + (size_t)t*DIMM))[tid] = out;
}

// ---------------- tf32 tensor-core GEMM, 128x128x16 tile ----------------
// C = epi( alpha*(A*B + bias) ) [+ R]
// EPI: 0 = bias only, 1 = bias + residual, 2 = gelu(bias)
// SPLIT: 1 = 3xTF32 (near-fp32 accuracy), 0 = single-pass tf32
// batched: bz -> A + (bz/Hn)*strideAb + (bz%Hn)*strideAh ; C + bz*strideC.
#define BM 128
#define BN 128
#define BK 16
#define ASTR 20      // Ah row stride (floats): conflict-free fragment loads
#define BSTR 136     // Bh row stride (floats): conflict-free fragment loads

template<int EPI, int SPLIT>
__global__ void __launch_bounds__(256)
mma_gemm(const float* __restrict__ A, const float* __restrict__ Bm,
         const float* __restrict__ bias, const float* __restrict__ R,
         float* __restrict__ C,
         int K, int lda, int ldb, int ldc, int ldr,
         long strideAb, long strideAh, int Hn, long strideC, float alpha)
{
    int bz = blockIdx.z;
    const float* Ab = A + (long)(bz / Hn)*strideAb + (long)(bz % Hn)*strideAh;
    float* Cb = C + (long)bz*strideC;
    int row0 = blockIdx.x*BM, col0 = blockIdx.y*BN;

    __shared__ float Ah[BM][ASTR];
    __shared__ float Bh[BK][BSTR];
    __shared__ float Al[SPLIT?BM:1][ASTR];
    __shared__ float Bl[SPLIT?BK:1][BSTR];

    int tid  = threadIdx.x;
    int lane = tid & 31;
    int warp = tid >> 5;
    int moff = (warp >> 2)*64;   // 2 warp rows
    int noff = (warp & 3)*32;    // 4 warp cols
    int t4   = lane >> 2;        // 0..7
    int tm4  = lane & 3;         // 0..3

    // global load mapping (float4 granularity)
    int a_row0 = tid >> 2,           a_c4 = (tid & 3)*4;     // + second: row+64
    int b_row0 = tid >> 5,           b_c4 = (tid & 31)*4;    // + second: row+8

    const float* aL0 = Ab + (long)(row0 + a_row0     )*lda + a_c4;
    const float* aL1 = Ab + (long)(row0 + a_row0 + 64)*lda + a_c4;
    const float* bL0 = Bm + (long)(b_row0    )*ldb + col0 + b_c4;
    const float* bL1 = Bm + (long)(b_row0 + 8)*ldb + col0 + b_c4;

    float acc[4][4][4];
    #pragma unroll
    for (int i=0;i<4;i++)
        #pragma unroll
        for (int j=0;j<4;j++)
            #pragma unroll
            for (int r=0;r<4;r++) acc[i][j][r]=0.f;

    float4 ra0 = *(const float4*)(aL0);
    float4 ra1 = *(const float4*)(aL1);
    float4 rb0 = *(const float4*)(bL0);
    float4 rb1 = *(const float4*)(bL1);

    for (int k0=0; k0<K; k0+=BK){
        // ---- store tile to SMEM (convert to tf32; split if requested) ----
        {
            float4 h0, h1;
            h0.x=tf32r(ra0.x); h0.y=tf32r(ra0.y); h0.z=tf32r(ra0.z); h0.w=tf32r(ra0.w);
            h1.x=tf32r(ra1.x); h1.y=tf32r(ra1.y); h1.z=tf32r(ra1.z); h1.w=tf32r(ra1.w);
            *(float4*)&Ah[a_row0   ][a_c4] = h0;
            *(float4*)&Ah[a_row0+64][a_c4] = h1;
            if (SPLIT){
                float4 l0, l1;
                l0.x=tf32r(ra0.x-h0.x); l0.y=tf32r(ra0.y-h0.y); l0.z=tf32r(ra0.z-h0.z); l0.w=tf32r(ra0.w-h0.w);
                l1.x=tf32r(ra1.x-h1.x); l1.y=tf32r(ra1.y-h1.y); l1.z=tf32r(ra1.z-h1.z); l1.w=tf32r(ra1.w-h1.w);
                *(float4*)&Al[a_row0   ][a_c4] = l0;
                *(float4*)&Al[a_row0+64][a_c4] = l1;
            }
            float4 g0, g1;
            g0.x=tf32r(rb0.x); g0.y=tf32r(rb0.y); g0.z=tf32r(rb0.z); g0.w=tf32r(rb0.w);
            g1.x=tf32r(rb1.x); g1.y=tf32r(rb1.y); g1.z=tf32r(rb1.z); g1.w=tf32r(rb1.w);
            *(float4*)&Bh[b_row0  ][b_c4] = g0;
            *(float4*)&Bh[b_row0+8][b_c4] = g1;
            if (SPLIT){
                float4 l0, l1;
                l0.x=tf32r(rb0.x-g0.x); l0.y=tf32r(rb0.y-g0.y); l0.z=tf32r(rb0.z-g0.z); l0.w=tf32r(rb0.w-g0.w);
                l1.x=tf32r(rb1.x-g1.x); l1.y=tf32r(rb1.y-g1.y); l1.z=tf32r(rb1.z-g1.z); l1.w=tf32r(rb1.w-g1.w);
                *(float4*)&Bl[b_row0  ][b_c4] = l0;
                *(float4*)&Bl[b_row0+8][b_c4] = l1;
            }
        }
        __syncthreads();

        // ---- prefetch next tile ----
        if (k0 + BK < K){
            ra0 = *(const float4*)(aL0 + k0 + BK);
            ra1 = *(const float4*)(aL1 + k0 + BK);
            rb0 = *(const float4*)(bL0 + (long)(k0+BK)*ldb);
            rb1 = *(const float4*)(bL1 + (long)(k0+BK)*ldb);
        }

        // ---- compute: two k8 sub-steps ----
        #pragma unroll
        for (int kk=0; kk<BK; kk+=8){
            float af[4][4], bf[4][2];
            #pragma unroll
            for (int mt=0; mt<4; mt++){
                int r = moff + mt*16 + t4;
                af[mt][0] = Ah[r  ][kk+tm4];
                af[mt][1] = Ah[r+8][kk+tm4];
                af[mt][2] = Ah[r  ][kk+tm4+4];
                af[mt][3] = Ah[r+8][kk+tm4+4];
            }
            #pragma unroll
            for (int nt=0; nt<4; nt++){
                int c = noff + nt*8 + t4;
                bf[nt][0] = Bh[kk+tm4  ][c];
                bf[nt][1] = Bh[kk+tm4+4][c];
            }
            #pragma unroll
            for (int mt=0; mt<4; mt++)
                #pragma unroll
                for (int nt=0; nt<4; nt++)
                    mma8(acc[mt][nt], af[mt], bf[nt]);

            if (SPLIT){
                float al[4][4], bl[4][2];
                #pragma unroll
                for (int mt=0; mt<4; mt++){
                    int r = moff + mt*16 + t4;
                    al[mt][0] = Al[r  ][kk+tm4];
                    al[mt][1] = Al[r+8][kk+tm4];
                    al[mt][2] = Al[r  ][kk+tm4+4];
                    al[mt][3] = Al[r+8][kk+tm4+4];
                }
                #pragma unroll
                for (int nt=0; nt<4; nt++){
                    int c = noff + nt*8 + t4;
                    bl[nt][0] = Bl[kk+tm4  ][c];
                    bl[nt][1] = Bl[kk+tm4+4][c];
                }
                #pragma unroll
                for (int mt=0; mt<4; mt++)
                    #pragma unroll
                    for (int nt=0; nt<4; nt++){
                        mma8(acc[mt][nt], af[mt], bl[nt]);   // hi*lo
                        mma8(acc[mt][nt], al[mt], bf[nt]);   // lo*hi
                    }
            }
        }
        __syncthreads();
    }

    // ---- epilogue ----
    #pragma unroll
    for (int nt=0; nt<4; nt++){
        int col = col0 + noff + nt*8 + 2*tm4;
        float b0 = bias ? bias[col]   : 0.f;
        float b1 = bias ? bias[col+1] : 0.f;
        #pragma unroll
        for (int mt=0; mt<4; mt++){
            int row = row0 + moff + mt*16 + t4;
            float v0 = (acc[mt][nt][0] + b0)*alpha;
            float v1 = (acc[mt][nt][1] + b1)*alpha;
            float v2 = (acc[mt][nt][2] + b0)*alpha;
            float v3 = (acc[mt][nt][3] + b1)*alpha;
            if (EPI==2){
                v0 = 0.5f*v0*(1.0f + erff(v0*RSQRT2));
                v1 = 0.5f*v1*(1.0f + erff(v1*RSQRT2));
                v2 = 0.5f*v2*(1.0f + erff(v2*RSQRT2));
                v3 = 0.5f*v3*(1.0f + erff(v3*RSQRT2));
            }
            if (EPI==1){
                v0 += R[(long)row*ldr + col];
                v1 += R[(long)row*ldr + col+1];
                v2 += R[(long)(row+8)*ldr + col];
                v3 += R[(long)(row+8)*ldr + col+1];
            }
            float2 p0 = make_float2(v0, v1);
            float2 p1 = make_float2(v2, v3);
            *(float2*)(&Cb[(long)row*ldc + col])     = p0;
            *(float2*)(&Cb[(long)(row+8)*ldc + col]) = p1;
        }
    }
}

// ---------------- proj transpose: [256,64] -> [64,256] ----------------
__global__ void transpose_proj(const float* __restrict__ proj, float* __restrict__ pt)
{
    int idx = blockIdx.x*256 + threadIdx.x;   // over 16384
    if (idx < NBF*DHEAD){
        int m = idx >> 6, k = idx & 63;
        pt[k*NBF + m] = proj[idx];
    }
}

// ---------------- zero / init per layer ----------------
__global__ void init_kernel()
{
    int idx = blockIdx.x*256 + threadIdx.x;
    if (idx < BH*NBF*DHEAD) g_ctx[idx] = 0.f;
    if (idx < BH*NBF)       g_ksum[idx] = 0.f;
    if (idx < BH)           g_kmax[idx] = f2ord(-INFINITY);
}

// ---------------- global max of kdash per (b,h) ----------------
__global__ void kmax_kernel(const float* __restrict__ kp)
{
    int bh = blockIdx.y;
    const float* p = kp + (size_t)bh*SEQ*NBF + (size_t)blockIdx.x*32768;
    int tid = threadIdx.x;
    float m = -INFINITY;
    for (int i=tid; i<32768; i+=256) m = fmaxf(m, p[i]);
    __shared__ float wred[8];
    int lane = tid & 31, w = tid >> 5;
    m = warpMax(m);
    if (lane==0) wred[w]=m;
    __syncthreads();
    if (tid==0){
        float t = -INFINITY;
        #pragma unroll
        for (int i=0;i<8;i++) t = fmaxf(t, wred[i]);
        atomicMax(&g_kmax[bh], f2ord(t));
    }
}

// ---------------- phi finish: dash -> ratio*(exp(dash - diag - max)+eps) ----------------
template<bool QMODE>
__global__ void phi_finish(const float* __restrict__ qk, float* __restrict__ dash)
{
    int bh = blockIdx.y, n = blockIdx.x;
    int b = bh >> 3, h = bh & 7;
    int tid = threadIdx.x;     // 256 = NBF
    float* row = dash + ((size_t)bh*SEQ + n)*NBF;
    float dv = row[tid];
    const float* qrow = qk + ((size_t)(b*SEQ + n))*DIMM + h*DHEAD;
    float q2 = (tid < DHEAD) ? qrow[tid]*qrow[tid] : 0.f;

    __shared__ float wred[8];
    __shared__ float res[2];
    int lane = tid & 31, w = tid >> 5;

    float s = warpSum(q2);
    if (lane==0) wred[w]=s;
    __syncthreads();
    if (tid==0){
        float t=0.f;
        #pragma unroll
        for (int i=0;i<8;i++) t += wred[i];
        res[0]=t;
    }
    __syncthreads();

    float mx;
    if (QMODE){
        float m = warpMax(dv);
        if (lane==0) wred[w]=m;
        __syncthreads();
        if (tid==0){
            float t=-INFINITY;
            #pragma unroll
            for (int i=0;i<8;i++) t = fmaxf(t, wred[i]);
            res[1]=t;
        }
        __syncthreads();
        mx = res[1];
    } else {
        mx = ord2f(g_kmax[bh]);
    }
    float diag = 0.5f*res[0];
    row[tid] = RATIO*(expf(dv - diag - mx) + PHI_EPS);
}

// ---------------- k_sum[bh][m] = sum_n kp ----------------
__global__ void ksum_kernel(const float* __restrict__ kp)
{
    int bh = blockIdx.y;
    int n0 = blockIdx.x*(SEQ/32);
    int tid = threadIdx.x;  // 256 = NBF
    const float* base = kp + ((size_t)bh*SEQ + n0)*NBF + tid;
    float s = 0.f;
    #pragma unroll 4
    for (int r=0; r<SEQ/32; r++) s += base[(size_t)r*NBF];
    atomicAdd(&g_ksum[bh*NBF + tid], s);
}

// ---------------- ctx[bh][m][d] = sum_n kp[bh][n][m]*v[b][n][h][d] (split-K + atomics) ----------------
__global__ void __launch_bounds__(256)
ctx_kernel(const float* __restrict__ kp, const float* __restrict__ v)
{
    int bh = blockIdx.z; int b = bh >> 3, h = bh & 7;
    const float* kpb = kp + (size_t)bh*SEQ*NBF;
    const float* vb  = v  + (size_t)b*SEQ*DIMM + h*DHEAD;
    int m0 = blockIdx.x*64;
    int n0 = blockIdx.y*(SEQ/8);  // 1024 per split

    __shared__ float Ks[16][64];
    __shared__ float Vs[16][64];
    int tid = threadIdx.x;
    int ty = tid >> 4, tx = tid & 15;
    int lr = tid >> 4, lc4 = (tid & 15)*4;

    float acc[4][4];
    #pragma unroll
    for (int i=0;i<4;i++)
        #pragma unroll
        for (int j=0;j<4;j++) acc[i][j]=0.f;

    for (int n=n0; n<n0+SEQ/8; n+=16){
        __syncthreads();
        *(float4*)(&Ks[lr][lc4]) = *(const float4*)(kpb + (size_t)(n+lr)*NBF + m0 + lc4);
        *(float4*)(&Vs[lr][lc4]) = *(const float4*)(vb  + (size_t)(n+lr)*DIMM + lc4);
        __syncthreads();
        #pragma unroll
        for (int kk=0;kk<16;kk++){
            float a[4], bb[4];
            #pragma unroll
            for (int i=0;i<4;i++) a[i]  = Ks[kk][ty*4+i];
            #pragma unroll
            for (int j=0;j<4;j++) bb[j] = Vs[kk][tx*4+j];
            #pragma unroll
            for (int i=0;i<4;i++)
                #pragma unroll
                for (int j=0;j<4;j++) acc[i][j] = fmaf(a[i], bb[j], acc[i][j]);
        }
    }
    #pragma unroll
    for (int i=0;i<4;i++)
        #pragma unroll
        for (int j=0;j<4;j++)
            atomicAdd(&g_ctx[((size_t)bh*NBF + m0 + ty*4 + i)*DHEAD + tx*4 + j], acc[i][j]);
}

// ---------------- d_inv[bh][n] = 1 / (qp[n,:] . k_sum) ----------------
__global__ void dinv_kernel(const float* __restrict__ qp)
{
    int bh = blockIdx.y;
    int n = blockIdx.x*8 + (threadIdx.x >> 5);
    int lane = threadIdx.x & 31;
    const float* row = qp + ((size_t)bh*SEQ + n)*NBF;
    const float* ks  = g_ksum + bh*NBF;
    float s = 0.f;
    #pragma unroll 2
    for (int j=lane; j<NBF; j+=32) s += row[j]*ks[j];
    s = warpSum(s);
    if (lane==0) g_dinv[(size_t)bh*SEQ + n] = 1.0f/s;
}

// ---------------- o = dinv * (qp @ ctx), scattered into [T, 512] ----------------
__global__ void __launch_bounds__(256, 2)
ogemm_kernel(const float* __restrict__ qp, float* __restrict__ o)
{
    int bh = blockIdx.z; int b = bh >> 3, h = bh & 7;
    const float* A  = qp    + (size_t)bh*SEQ*NBF;
    const float* Bm = g_ctx + (size_t)bh*NBF*DHEAD;
    int row0 = blockIdx.x*128;

    __shared__ float As[8][128];
    __shared__ float Bs[8][64];
    int tid = threadIdx.x;
    int ty = tid >> 4, tx = tid & 15;

    float acc[8][4];
    #pragma unroll
    for (int i=0;i<8;i++)
        #pragma unroll
        for (int j=0;j<4;j++) acc[i][j]=0.f;

    for (int k0=0; k0<NBF; k0+=8){
        float4 av = *(const float4*)(A + (size_t)(row0 + (tid>>1))*NBF + k0 + (tid&1)*4);
        __syncthreads();
        {
            int arow = tid >> 1, acol4 = (tid & 1)*4;
            As[acol4+0][arow]=av.x; As[acol4+1][arow]=av.y;
            As[acol4+2][arow]=av.z; As[acol4+3][arow]=av.w;
        }
        if (tid < 128)
            *(float4*)(&Bs[tid>>4][(tid&15)*4]) =
                *(const float4*)(Bm + (size_t)(k0 + (tid>>4))*DHEAD + (tid&15)*4);
        __syncthreads();
        #pragma unroll
        for (int kk=0;kk<8;kk++){
            float a[8], bb[4];
            #pragma unroll
            for (int i=0;i<8;i++) a[i]  = As[kk][ty*8+i];
            #pragma unroll
            for (int j=0;j<4;j++) bb[j] = Bs[kk][tx*4+j];
            #pragma unroll
            for (int i=0;i<8;i++)
                #pragma unroll
                for (int j=0;j<4;j++) acc[i][j] = fmaf(a[i], bb[j], acc[i][j]);
        }
    }
    #pragma unroll
    for (int i=0;i<8;i++){
        int n = row0 + ty*8 + i;
        float di = g_dinv[(size_t)bh*SEQ + n];
        #pragma unroll
        for (int j=0;j<4;j++)
            o[((size_t)(b*SEQ + n))*DIMM + h*DHEAD + tx*4 + j] = acc[i][j]*di;
    }
}

// ---------------- host driver ----------------
extern "C" void kernel_launch(void* const* d_in, const int* in_sizes, int n_in,
                              void* d_out, int out_size)
{
    const float* ln1_g = (const float*)d_in[1];
    const float* ln1_b = (const float*)d_in[2];
    const float* ln2_g = (const float*)d_in[3];
    const float* ln2_b = (const float*)d_in[4];
    const float* Wq    = (const float*)d_in[5];
    const float* bq    = (const float*)d_in[6];
    const float* Wk    = (const float*)d_in[7];
    const float* bk    = (const float*)d_in[8];
    const float* Wv    = (const float*)d_in[9];
    const float* bv    = (const float*)d_in[10];
    const float* Wo    = (const float*)d_in[11];
    const float* bo    = (const float*)d_in[12];
    const float* proj  = (const float*)d_in[13];
    const float* W1    = (const float*)d_in[14];
    const float* b1    = (const float*)d_in[15];
    const float* W2    = (const float*)d_in[16];
    const float* b2    = (const float*)d_in[17];

    float* x = (float*)d_out;
    cudaMemcpyAsync(x, d_in[0], TD*sizeof(float), cudaMemcpyDeviceToDevice);

    float* arena;
    cudaGetSymbolAddress((void**)&arena, g_arena);
    float* py  = arena;            // TD
    float* pq  = arena + TD;       // TD
    float* pk  = arena + 2*TD;     // TD
    float* pv  = arena + 3*TD;     // TD
    float* po  = arena + 4*TD;     // TD
    float* ph  = arena + TD;       // 4*TD, aliases q..o (FF phase only)
    float* pqp = arena + 5*TD;     // 4*TD
    float* pkp = arena + 9*TD;     // 4*TD
    float* pprojT;
    cudaGetSymbolAddress((void**)&pprojT, g_projT);

    for (int i=0; i<DEPTH; i++){
        // ---- attention block ----
        ln_kernel<<<TOK,128>>>(x, ln1_g + i*DIMM, ln1_b + i*DIMM, py);

        dim3 gQKV(TOK/128, DIMM/128, 1);
        // Q, K feed the exp path -> 3xTF32; V feeds only the delta -> single tf32
        mma_gemm<0,1><<<gQKV,256>>>(py, Wq + (size_t)i*DIMM*DIMM, bq + i*DIMM, nullptr, pq,
                                    DIMM, DIMM, DIMM, DIMM, 0, 0, 0, 1, 0, NORMALIZER);
        mma_gemm<0,1><<<gQKV,256>>>(py, Wk + (size_t)i*DIMM*DIMM, bk + i*DIMM, nullptr, pk,
                                    DIMM, DIMM, DIMM, DIMM, 0, 0, 0, 1, 0, NORMALIZER);
        mma_gemm<0,0><<<gQKV,256>>>(py, Wv + (size_t)i*DIMM*DIMM, bv + i*DIMM, nullptr, pv,
                                    DIMM, DIMM, DIMM, DIMM, 0, 0, 0, 1, 0, 1.0f);

        transpose_proj<<<64,256>>>(proj + (size_t)i*NBF*DHEAD, pprojT);

        // kdash = k_head @ projT  (batched over (b,h)) -- exp path -> 3xTF32
        dim3 gDASH(SEQ/128, NBF/128, BH);
        mma_gemm<0,1><<<gDASH,256>>>(pk, pprojT, nullptr, nullptr, pkp,
                                     DHEAD, DIMM, NBF, NBF, 0,
                                     (long)SEQ*DIMM, DHEAD, HEADS, (long)SEQ*NBF, 1.0f);
        init_kernel<<<2048,256>>>();
        kmax_kernel<<<dim3(64,BH),256>>>(pkp);
        phi_finish<false><<<dim3(SEQ,BH),256>>>(pk, pkp);
        ksum_kernel<<<dim3(32,BH),256>>>(pkp);

        // qdash = q_head @ projT, then per-row finish
        mma_gemm<0,1><<<gDASH,256>>>(pq, pprojT, nullptr, nullptr, pqp,
                                     DHEAD, DIMM, NBF, NBF, 0,
                                     (long)SEQ*DIMM, DHEAD, HEADS, (long)SEQ*NBF, 1.0f);
        phi_finish<true><<<dim3(SEQ,BH),256>>>(pq, pqp);

        ctx_kernel<<<dim3(NBF/64, 8, BH),256>>>(pkp, pv);
        dinv_kernel<<<dim3(SEQ/8, BH),256>>>(pqp);
        ogemm_kernel<<<dim3(SEQ/128, 1, BH),256>>>(pqp, po);

        // x += o @ Wo + bo
        mma_gemm<1,0><<<gQKV,256>>>(po, Wo + (size_t)i*DIMM*DIMM, bo + i*DIMM, x, x,
                                    DIMM, DIMM, DIMM, DIMM, DIMM, 0, 0, 1, 0, 1.0f);

        // ---- feed-forward block ----
        ln_kernel<<<TOK,128>>>(x, ln2_g + i*DIMM, ln2_b + i*DIMM, py);

        dim3 gW1(TOK/128, FFD/128, 1);
        mma_gemm<2,0><<<gW1,256>>>(py, W1 + (size_t)i*DIMM*FFD, b1 + i*FFD, nullptr, ph,
                                   DIMM, DIMM, FFD, FFD, 0, 0, 0, 1, 0, 1.0f);
        dim3 gW2(TOK/128, DIMM/128, 1);
        mma_gemm<1,0><<<gW2,256>>>(ph, W2 + (size_t)i*FFD*DIMM, b2 + i*DIMM, x, x,
                                   FFD, FFD, DIMM, DIMM, DIMM, 0, 0, 1, 0, 1.0f);
    }
}

// round 7
// speedup vs baseline: 1.7519x; 1.0585x over previous
#include <cuda_runtime.h>
#include <math.h>

// ---------------- problem constants ----------------
#define DEPTH  2
#define NBATCH 4
#define SEQ    8192
#define DIMM   512
#define HEADS  8
#define DHEAD  64
#define NBF    256          // random features m
#define FFD    2048
#define TOK    (NBATCH*SEQ) // 32768
#define BH     (NBATCH*HEADS) // 32

#define NORMALIZER 0.3535533905932738f   // 64^-0.25
#define RATIO      0.0625f               // 256^-0.5
#define PHI_EPS    1e-4f
#define LN_EPS     1e-5f
#define RSQRT2     0.70710678118654752f

// ---------------- device scratch (allocation-free) ----------------
#define TD ((size_t)TOK*DIMM)
__device__ float g_arena[13*TD];
__device__ float g_projT[DHEAD*NBF];
__device__ float g_ksum[BH*NBF];
__device__ int   g_kmax[BH];
__device__ float g_ctx[BH*NBF*DHEAD];
__device__ float g_dinv[BH*SEQ];

// ---------------- helpers ----------------
__device__ __forceinline__ float warpSum(float v){
    #pragma unroll
    for (int o=16;o;o>>=1) v += __shfl_xor_sync(0xffffffffu, v, o);
    return v;
}
__device__ __forceinline__ float warpMax(float v){
    #pragma unroll
    for (int o=16;o;o>>=1) v = fmaxf(v, __shfl_xor_sync(0xffffffffu, v, o));
    return v;
}
__device__ __forceinline__ int   f2ord(float f){ int i=__float_as_int(f); return i ^ ((i>>31) & 0x7fffffff); }
__device__ __forceinline__ float ord2f(int i){ return __int_as_float(i ^ ((i>>31) & 0x7fffffff)); }

__device__ __forceinline__ float tf32r(float x){
    unsigned u;
    asm("cvt.rna.tf32.f32 %0, %1;" : "=r"(u) : "f"(x));
    return __uint_as_float(u);
}

__device__ __forceinline__ void mma8(float* d, const float* a, const float* b){
    asm volatile(
      "mma.sync.aligned.m16n8k8.row.col.f32.tf32.tf32.f32 "
      "{%0,%1,%2,%3},{%4,%5,%6,%7},{%8,%9},{%0,%1,%2,%3};"
      : "+f"(d[0]),"+f"(d[1]),"+f"(d[2]),"+f"(d[3])
      : "r"(__float_as_uint(a[0])),"r"(__float_as_uint(a[1])),
        "r"(__float_as_uint(a[2])),"r"(__float_as_uint(a[3])),
        "r"(__float_as_uint(b[0])),"r"(__float_as_uint(b[1])));
}

// ldmatrix x4: loads the full m16k8 tf32 A-fragment (a0..a3) in one instruction.
__device__ __forceinline__ void ldmx4(float* f, unsigned a){
    unsigned r0,r1,r2,r3;
    asm volatile("ldmatrix.sync.aligned.m8n8.x4.shared.b16 {%0,%1,%2,%3}, [%4];"
                 : "=r"(r0),"=r"(r1),"=r"(r2),"=r"(r3) : "r"(a));
    f[0]=__uint_as_float(r0); f[1]=__uint_as_float(r1);
    f[2]=__uint_as_float(r2); f[3]=__uint_as_float(r3);
}

// ---------------- layernorm: one block per token ----------------
__global__ void ln_kernel(const float* __restrict__ x, const float* __restrict__ g,
                          const float* __restrict__ b, float* __restrict__ y)
{
    int t = blockIdx.x;
    int tid = threadIdx.x;              // 128 threads, 4 floats each
    const float4* xr = (const float4*)(x + (size_t)t*DIMM);
    float4 v = xr[tid];
    __shared__ float wred[4];
    __shared__ float stats[2];
    int lane = tid & 31, w = tid >> 5;

    float s = v.x+v.y+v.z+v.w;
    s = warpSum(s);
    if (lane==0) wred[w]=s;
    __syncthreads();
    if (tid==0) stats[0] = (wred[0]+wred[1]+wred[2]+wred[3]) * (1.0f/DIMM);
    __syncthreads();
    float mean = stats[0];

    float dx0=v.x-mean, dx1=v.y-mean, dx2=v.z-mean, dx3=v.w-mean;
    float s2 = dx0*dx0+dx1*dx1+dx2*dx2+dx3*dx3;
    s2 = warpSum(s2);
    if (lane==0) wred[w]=s2;
    __syncthreads();
    if (tid==0) stats[1] = (wred[0]+wred[1]+wred[2]+wred[3]) * (1.0f/DIMM);
    __syncthreads();
    float inv = rsqrtf(stats[1] + LN_EPS);

    float4 gv = ((const float4*)g)[tid];
    float4 bv = ((const float4*)b)[tid];
    float4 out;
    out.x = dx0*inv*gv.x + bv.x;
    out.y = dx1*inv*gv.y + bv.y;
    out.z = dx2*inv*gv.z + bv.z;
    out.w = dx3*inv*gv.w + bv.w;
    ((float4*)(y + (size_t)t*DIMM))[tid] = out;
}

// ---------------- tf32 tensor-core GEMM, 128x128x16 tile ----------------
// EPI: 0 = bias, 1 = bias + residual, 2 = gelu(bias), 3 = write + block max -> g_kmax[bz]
// SPLIT: 1 = 3xTF32 (near-fp32 accuracy), 0 = single-pass tf32
#define BM 128
#define BN 128
#define BK 16
#define ASTR 20      // Ah row stride (floats): ldmatrix row-starts hit disjoint banks
#define BSTR 136     // Bh row stride (floats): conflict-free scalar fragment loads

template<int EPI, int SPLIT>
__global__ void __launch_bounds__(256)
mma_gemm(const float* __restrict__ A, const float* __restrict__ Bm,
         const float* __restrict__ bias, const float* __restrict__ R,
         float* __restrict__ C,
         int K, int lda, int ldb, int ldc, int ldr,
         long strideAb, long strideAh, int Hn, long strideC, float alpha)
{
    int bz = blockIdx.z;
    const float* Ab = A + (long)(bz / Hn)*strideAb + (long)(bz % Hn)*strideAh;
    float* Cb = C + (long)bz*strideC;
    int row0 = blockIdx.x*BM, col0 = blockIdx.y*BN;

    __shared__ float Ah[BM][ASTR];
    __shared__ float Bh[BK][BSTR];
    __shared__ float Al[SPLIT?BM:1][ASTR];
    __shared__ float Bl[SPLIT?BK:1][BSTR];
    __shared__ float rmax[8];

    int tid  = threadIdx.x;
    int lane = tid & 31;
    int warp = tid >> 5;
    int moff = (warp >> 2)*64;   // 2 warp rows
    int noff = (warp & 3)*32;    // 4 warp cols
    int t4   = lane >> 2;        // 0..7
    int tm4  = lane & 3;         // 0..3

    // ldmatrix per-thread source: grp 0..3 -> (row block, col half)
    int grp = lane >> 3, rr = lane & 7;
    int arow_ld = moff + rr + (grp & 1)*8;
    int acol_ld = (grp >> 1)*4;
    unsigned aAddr  = (unsigned)__cvta_generic_to_shared(&Ah[0][0])
                    + (unsigned)((arow_ld*ASTR + acol_ld)*4);
    unsigned alAddr = (unsigned)__cvta_generic_to_shared(&Al[0][0])
                    + (unsigned)((arow_ld*ASTR + acol_ld)*4);

    // B fragment base pointers (compile-time offsets added in the loop)
    const float* bPt  = &Bh[0][0] + tm4*BSTR + noff + t4;
    const float* blPt = &Bl[0][0] + tm4*BSTR + noff + t4;

    // global load mapping (float4 granularity)
    int a_row0 = tid >> 2,           a_c4 = (tid & 3)*4;     // + second: row+64
    int b_row0 = tid >> 5,           b_c4 = (tid & 31)*4;    // + second: row+8

    const float* aL0 = Ab + (long)(row0 + a_row0     )*lda + a_c4;
    const float* aL1 = Ab + (long)(row0 + a_row0 + 64)*lda + a_c4;
    const float* bL0 = Bm + (long)(b_row0    )*ldb + col0 + b_c4;
    const float* bL1 = Bm + (long)(b_row0 + 8)*ldb + col0 + b_c4;

    float acc[4][4][4];
    #pragma unroll
    for (int i=0;i<4;i++)
        #pragma unroll
        for (int j=0;j<4;j++)
            #pragma unroll
            for (int r=0;r<4;r++) acc[i][j][r]=0.f;

    float4 ra0 = *(const float4*)(aL0);
    float4 ra1 = *(const float4*)(aL1);
    float4 rb0 = *(const float4*)(bL0);
    float4 rb1 = *(const float4*)(bL1);

    for (int k0=0; k0<K; k0+=BK){
        // ---- store tile to SMEM (convert to tf32; split if requested) ----
        {
            float4 h0, h1;
            h0.x=tf32r(ra0.x); h0.y=tf32r(ra0.y); h0.z=tf32r(ra0.z); h0.w=tf32r(ra0.w);
            h1.x=tf32r(ra1.x); h1.y=tf32r(ra1.y); h1.z=tf32r(ra1.z); h1.w=tf32r(ra1.w);
            *(float4*)&Ah[a_row0   ][a_c4] = h0;
            *(float4*)&Ah[a_row0+64][a_c4] = h1;
            if (SPLIT){
                float4 l0, l1;
                l0.x=tf32r(ra0.x-h0.x); l0.y=tf32r(ra0.y-h0.y); l0.z=tf32r(ra0.z-h0.z); l0.w=tf32r(ra0.w-h0.w);
                l1.x=tf32r(ra1.x-h1.x); l1.y=tf32r(ra1.y-h1.y); l1.z=tf32r(ra1.z-h1.z); l1.w=tf32r(ra1.w-h1.w);
                *(float4*)&Al[a_row0   ][a_c4] = l0;
                *(float4*)&Al[a_row0+64][a_c4] = l1;
            }
            float4 g0, g1;
            g0.x=tf32r(rb0.x); g0.y=tf32r(rb0.y); g0.z=tf32r(rb0.z); g0.w=tf32r(rb0.w);
            g1.x=tf32r(rb1.x); g1.y=tf32r(rb1.y); g1.z=tf32r(rb1.z); g1.w=tf32r(rb1.w);
            *(float4*)&Bh[b_row0  ][b_c4] = g0;
            *(float4*)&Bh[b_row0+8][b_c4] = g1;
            if (SPLIT){
                float4 l0, l1;
                l0.x=tf32r(rb0.x-g0.x); l0.y=tf32r(rb0.y-g0.y); l0.z=tf32r(rb0.z-g0.z); l0.w=tf32r(rb0.w-g0.w);
                l1.x=tf32r(rb1.x-g1.x); l1.y=tf32r(rb1.y-g1.y); l1.z=tf32r(rb1.z-g1.z); l1.w=tf32r(rb1.w-g1.w);
                *(float4*)&Bl[b_row0  ][b_c4] = l0;
                *(float4*)&Bl[b_row0+8][b_c4] = l1;
            }
        }
        __syncthreads();

        // ---- prefetch next tile ----
        if (k0 + BK < K){
            ra0 = *(const float4*)(aL0 + k0 + BK);
            ra1 = *(const float4*)(aL1 + k0 + BK);
            rb0 = *(const float4*)(bL0 + (long)(k0+BK)*ldb);
            rb1 = *(const float4*)(bL1 + (long)(k0+BK)*ldb);
        }

        // ---- compute: two k8 sub-steps ----
        #pragma unroll
        for (int kk=0; kk<BK; kk+=8){
            float af[4][4], bf[4][2];
            #pragma unroll
            for (int mt=0; mt<4; mt++)
                ldmx4(af[mt], aAddr + (unsigned)((mt*16*ASTR + kk)*4));
            #pragma unroll
            for (int nt=0; nt<4; nt++){
                bf[nt][0] = bPt[(kk  )*BSTR + nt*8];
                bf[nt][1] = bPt[(kk+4)*BSTR + nt*8];
            }
            #pragma unroll
            for (int mt=0; mt<4; mt++)
                #pragma unroll
                for (int nt=0; nt<4; nt++)
                    mma8(acc[mt][nt], af[mt], bf[nt]);

            if (SPLIT){
                float al[4][4], bl[4][2];
                #pragma unroll
                for (int mt=0; mt<4; mt++)
                    ldmx4(al[mt], alAddr + (unsigned)((mt*16*ASTR + kk)*4));
                #pragma unroll
                for (int nt=0; nt<4; nt++){
                    bl[nt][0] = blPt[(kk  )*BSTR + nt*8];
                    bl[nt][1] = blPt[(kk+4)*BSTR + nt*8];
                }
                #pragma unroll
                for (int mt=0; mt<4; mt++)
                    #pragma unroll
                    for (int nt=0; nt<4; nt++){
                        mma8(acc[mt][nt], af[mt], bl[nt]);   // hi*lo
                        mma8(acc[mt][nt], al[mt], bf[nt]);   // lo*hi
                    }
            }
        }
        __syncthreads();
    }

    // ---- epilogue ----
    float vmax = -INFINITY;
    #pragma unroll
    for (int nt=0; nt<4; nt++){
        int col = col0 + noff + nt*8 + 2*tm4;
        float b0 = bias ? bias[col]   : 0.f;
        float b1 = bias ? bias[col+1] : 0.f;
        #pragma unroll
        for (int mt=0; mt<4; mt++){
            int row = row0 + moff + mt*16 + t4;
            float v0 = (acc[mt][nt][0] + b0)*alpha;
            float v1 = (acc[mt][nt][1] + b1)*alpha;
            float v2 = (acc[mt][nt][2] + b0)*alpha;
            float v3 = (acc[mt][nt][3] + b1)*alpha;
            if (EPI==2){
                v0 = 0.5f*v0*(1.0f + erff(v0*RSQRT2));
                v1 = 0.5f*v1*(1.0f + erff(v1*RSQRT2));
                v2 = 0.5f*v2*(1.0f + erff(v2*RSQRT2));
                v3 = 0.5f*v3*(1.0f + erff(v3*RSQRT2));
            }
            if (EPI==1){
                v0 += R[(long)row*ldr + col];
                v1 += R[(long)row*ldr + col+1];
                v2 += R[(long)(row+8)*ldr + col];
                v3 += R[(long)(row+8)*ldr + col+1];
            }
            if (EPI==3){
                vmax = fmaxf(vmax, fmaxf(fmaxf(v0,v1), fmaxf(v2,v3)));
            }
            float2 p0 = make_float2(v0, v1);
            float2 p1 = make_float2(v2, v3);
            *(float2*)(&Cb[(long)row*ldc + col])     = p0;
            *(float2*)(&Cb[(long)(row+8)*ldc + col]) = p1;
        }
    }
    if (EPI==3){
        float m = warpMax(vmax);
        if (lane==0) rmax[warp]=m;
        __syncthreads();
        if (tid==0){
            float t=-INFINITY;
            #pragma unroll
            for (int i=0;i<8;i++) t = fmaxf(t, rmax[i]);
            atomicMax(&g_kmax[blockIdx.z], f2ord(t));
        }
    }
}

// ---------------- proj transpose: [256,64] -> [64,256] ----------------
__global__ void transpose_proj(const float* __restrict__ proj, float* __restrict__ pt)
{
    int idx = blockIdx.x*256 + threadIdx.x;   // over 16384
    if (idx < NBF*DHEAD){
        int m = idx >> 6, k = idx & 63;
        pt[k*NBF + m] = proj[idx];
    }
}

// ---------------- zero / init per layer (must run BEFORE dash-k GEMM) ----------------
__global__ void init_kernel()
{
    int idx = blockIdx.x*256 + threadIdx.x;
    if (idx < BH*NBF*DHEAD) g_ctx[idx] = 0.f;
    if (idx < BH*NBF)       g_ksum[idx] = 0.f;
    if (idx < BH)           g_kmax[idx] = f2ord(-INFINITY);
}

// ---------------- phi finish ----------------
// QMODE=false: uses global k-max (accumulated in dash-k epilogue)
// QMODE=true : per-row max; ALSO computes d_inv (needs g_ksum ready)
template<bool QMODE>
__global__ void phi_finish(const float* __restrict__ qk, float* __restrict__ dash)
{
    int bh = blockIdx.y, n = blockIdx.x;
    int b = bh >> 3, h = bh & 7;
    int tid = threadIdx.x;     // 256 = NBF
    float* row = dash + ((size_t)bh*SEQ + n)*NBF;
    float dv = row[tid];
    const float* qrow = qk + ((size_t)(b*SEQ + n))*DIMM + h*DHEAD;
    float q2 = (tid < DHEAD) ? qrow[tid]*qrow[tid] : 0.f;

    __shared__ float wred[8];
    __shared__ float res[2];
    int lane = tid & 31, w = tid >> 5;

    float s = warpSum(q2);
    if (lane==0) wred[w]=s;
    __syncthreads();
    if (tid==0){
        float t=0.f;
        #pragma unroll
        for (int i=0;i<8;i++) t += wred[i];
        res[0]=t;
    }
    __syncthreads();

    float mx;
    if (QMODE){
        float m = warpMax(dv);
        if (lane==0) wred[w]=m;
        __syncthreads();
        if (tid==0){
            float t=-INFINITY;
            #pragma unroll
            for (int i=0;i<8;i++) t = fmaxf(t, wred[i]);
            res[1]=t;
        }
        __syncthreads();
        mx = res[1];
    } else {
        mx = ord2f(g_kmax[bh]);
    }
    float diag = 0.5f*res[0];
    float val = RATIO*(expf(dv - diag - mx) + PHI_EPS);
    row[tid] = val;

    if (QMODE){
        // fused d_inv: 1 / dot(qp_row, k_sum)
        float contrib = val * g_ksum[bh*NBF + tid];
        float s2 = warpSum(contrib);
        if (lane==0) wred[w]=s2;
        __syncthreads();
        if (tid==0){
            float t=0.f;
            #pragma unroll
            for (int i=0;i<8;i++) t += wred[i];
            g_dinv[(size_t)bh*SEQ + n] = 1.0f/t;
        }
    }
}

// ---------------- k_sum[bh][m] = sum_n kp ----------------
__global__ void ksum_kernel(const float* __restrict__ kp)
{
    int bh = blockIdx.y;
    int n0 = blockIdx.x*(SEQ/32);
    int tid = threadIdx.x;  // 256 = NBF
    const float* base = kp + ((size_t)bh*SEQ + n0)*NBF + tid;
    float s = 0.f;
    #pragma unroll 4
    for (int r=0; r<SEQ/32; r++) s += base[(size_t)r*NBF];
    atomicAdd(&g_ksum[bh*NBF + tid], s);
}

// ---------------- ctx[bh][m][d] = sum_n kp[bh][n][m]*v[b][n][h][d] (split-K + atomics) ----------------
__global__ void __launch_bounds__(256)
ctx_kernel(const float* __restrict__ kp, const float* __restrict__ v)
{
    int bh = blockIdx.z; int b = bh >> 3, h = bh & 7;
    const float* kpb = kp + (size_t)bh*SEQ*NBF;
    const float* vb  = v  + (size_t)b*SEQ*DIMM + h*DHEAD;
    int m0 = blockIdx.x*64;
    int n0 = blockIdx.y*(SEQ/8);  // 1024 per split

    __shared__ float Ks[16][64];
    __shared__ float Vs[16][64];
    int tid = threadIdx.x;
    int ty = tid >> 4, tx = tid & 15;
    int lr = tid >> 4, lc4 = (tid & 15)*4;

    float acc[4][4];
    #pragma unroll
    for (int i=0;i<4;i++)
        #pragma unroll
        for (int j=0;j<4;j++) acc[i][j]=0.f;

    for (int n=n0; n<n0+SEQ/8; n+=16){
        __syncthreads();
        *(float4*)(&Ks[lr][lc4]) = *(const float4*)(kpb + (size_t)(n+lr)*NBF + m0 + lc4);
        *(float4*)(&Vs[lr][lc4]) = *(const float4*)(vb  + (size_t)(n+lr)*DIMM + lc4);
        __syncthreads();
        #pragma unroll
        for (int kk=0;kk<16;kk++){
            float a[4], bb[4];
            #pragma unroll
            for (int i=0;i<4;i++) a[i]  = Ks[kk][ty*4+i];
            #pragma unroll
            for (int j=0;j<4;j++) bb[j] = Vs[kk][tx*4+j];
            #pragma unroll
            for (int i=0;i<4;i++)
                #pragma unroll
                for (int j=0;j<4;j++) acc[i][j] = fmaf(a[i], bb[j], acc[i][j]);
        }
    }
    #pragma unroll
    for (int i=0;i<4;i++)
        #pragma unroll
        for (int j=0;j<4;j++)
            atomicAdd(&g_ctx[((size_t)bh*NBF + m0 + ty*4 + i)*DHEAD + tx*4 + j], acc[i][j]);
}

// ---------------- o = dinv * (qp @ ctx), scattered into [T, 512] ----------------
__global__ void __launch_bounds__(256, 2)
ogemm_kernel(const float* __restrict__ qp, float* __restrict__ o)
{
    int bh = blockIdx.z; int b = bh >> 3, h = bh & 7;
    const float* A  = qp    + (size_t)bh*SEQ*NBF;
    const float* Bm = g_ctx + (size_t)bh*NBF*DHEAD;
    int row0 = blockIdx.x*128;

    __shared__ float As[8][128];
    __shared__ float Bs[8][64];
    int tid = threadIdx.x;
    int ty = tid >> 4, tx = tid & 15;

    float acc[8][4];
    #pragma unroll
    for (int i=0;i<8;i++)
        #pragma unroll
        for (int j=0;j<4;j++) acc[i][j]=0.f;

    for (int k0=0; k0<NBF; k0+=8){
        float4 av = *(const float4*)(A + (size_t)(row0 + (tid>>1))*NBF + k0 + (tid&1)*4);
        __syncthreads();
        {
            int arow = tid >> 1, acol4 = (tid & 1)*4;
            As[acol4+0][arow]=av.x; As[acol4+1][arow]=av.y;
            As[acol4+2][arow]=av.z; As[acol4+3][arow]=av.w;
        }
        if (tid < 128)
            *(float4*)(&Bs[tid>>4][(tid&15)*4]) =
                *(const float4*)(Bm + (size_t)(k0 + (tid>>4))*DHEAD + (tid&15)*4);
        __syncthreads();
        #pragma unroll
        for (int kk=0;kk<8;kk++){
            float a[8], bb[4];
            #pragma unroll
            for (int i=0;i<8;i++) a[i]  = As[kk][ty*8+i];
            #pragma unroll
            for (int j=0;j<4;j++) bb[j] = Bs[kk][tx*4+j];
            #pragma unroll
            for (int i=0;i<8;i++)
                #pragma unroll
                for (int j=0;j<4;j++) acc[i][j] = fmaf(a[i], bb[j], acc[i][j]);
        }
    }
    #pragma unroll
    for (int i=0;i<8;i++){
        int n = row0 + ty*8 + i;
        float di = g_dinv[(size_t)bh*SEQ + n];
        #pragma unroll
        for (int j=0;j<4;j++)
            o[((size_t)(b*SEQ + n))*DIMM + h*DHEAD + tx*4 + j] = acc[i][j]*di;
    }
}

// ---------------- host driver ----------------
extern "C" void kernel_launch(void* const* d_in, const int* in_sizes, int n_in,
                              void* d_out, int out_size)
{
    const float* ln1_g = (const float*)d_in[1];
    const float* ln1_b = (const float*)d_in[2];
    const float* ln2_g = (const float*)d_in[3];
    const float* ln2_b = (const float*)d_in[4];
    const float* Wq    = (const float*)d_in[5];
    const float* bq    = (const float*)d_in[6];
    const float* Wk    = (const float*)d_in[7];
    const float* bk    = (const float*)d_in[8];
    const float* Wv    = (const float*)d_in[9];
    const float* bv    = (const float*)d_in[10];
    const float* Wo    = (const float*)d_in[11];
    const float* bo    = (const float*)d_in[12];
    const float* proj  = (const float*)d_in[13];
    const float* W1    = (const float*)d_in[14];
    const float* b1    = (const float*)d_in[15];
    const float* W2    = (const float*)d_in[16];
    const float* b2    = (const float*)d_in[17];

    float* x = (float*)d_out;
    cudaMemcpyAsync(x, d_in[0], TD*sizeof(float), cudaMemcpyDeviceToDevice);

    float* arena;
    cudaGetSymbolAddress((void**)&arena, g_arena);
    float* py  = arena;            // TD
    float* pq  = arena + TD;       // TD
    float* pk  = arena + 2*TD;     // TD
    float* pv  = arena + 3*TD;     // TD
    float* po  = arena + 4*TD;     // TD
    float* ph  = arena + TD;       // 4*TD, aliases q..o (FF phase only)
    float* pqp = arena + 5*TD;     // 4*TD
    float* pkp = arena + 9*TD;     // 4*TD
    float* pprojT;
    cudaGetSymbolAddress((void**)&pprojT, g_projT);

    for (int i=0; i<DEPTH; i++){
        // ---- attention block ----
        ln_kernel<<<TOK,128>>>(x, ln1_g + i*DIMM, ln1_b + i*DIMM, py);

        dim3 gQKV(TOK/128, DIMM/128, 1);
        // Q, K feed the exp path -> 3xTF32; V feeds only the delta -> single tf32
        mma_gemm<0,1><<<gQKV,256>>>(py, Wq + (size_t)i*DIMM*DIMM, bq + i*DIMM, nullptr, pq,
                                    DIMM, DIMM, DIMM, DIMM, 0, 0, 0, 1, 0, NORMALIZER);
        mma_gemm<0,1><<<gQKV,256>>>(py, Wk + (size_t)i*DIMM*DIMM, bk + i*DIMM, nullptr, pk,
                                    DIMM, DIMM, DIMM, DIMM, 0, 0, 0, 1, 0, NORMALIZER);
        mma_gemm<0,0><<<gQKV,256>>>(py, Wv + (size_t)i*DIMM*DIMM, bv + i*DIMM, nullptr, pv,
                                    DIMM, DIMM, DIMM, DIMM, 0, 0, 0, 1, 0, 1.0f);

        transpose_proj<<<64,256>>>(proj + (size_t)i*NBF*DHEAD, pprojT);
        init_kernel<<<2048,256>>>();   // resets ctx/ksum/kmax BEFORE dash-k (kmax fused there)

        // kdash = k_head @ projT  (batched over (b,h)); EPI=3 fuses global k-max
        dim3 gDASH(SEQ/128, NBF/128, BH);
        mma_gemm<3,1><<<gDASH,256>>>(pk, pprojT, nullptr, nullptr, pkp,
                                     DHEAD, DIMM, NBF, NBF, 0,
                                     (long)SEQ*DIMM, DHEAD, HEADS, (long)SEQ*NBF, 1.0f);
        phi_finish<false><<<dim3(SEQ,BH),256>>>(pk, pkp);
        ksum_kernel<<<dim3(32,BH),256>>>(pkp);

        // qdash = q_head @ projT, then per-row finish (+ fused d_inv; needs ksum)
        mma_gemm<0,1><<<gDASH,256>>>(pq, pprojT, nullptr, nullptr, pqp,
                                     DHEAD, DIMM, NBF, NBF, 0,
                                     (long)SEQ*DIMM, DHEAD, HEADS, (long)SEQ*NBF, 1.0f);
        phi_finish<true><<<dim3(SEQ,BH),256>>>(pq, pqp);

        ctx_kernel<<<dim3(NBF/64, 8, BH),256>>>(pkp, pv);
        ogemm_kernel<<<dim3(SEQ/128, 1, BH),256>>>(pqp, po);

        // x += o @ Wo + bo
        mma_gemm<1,0><<<gQKV,256>>>(po, Wo + (size_t)i*DIMM*DIMM, bo + i*DIMM, x, x,
                                    DIMM, DIMM, DIMM, DIMM, DIMM, 0, 0, 1, 0, 1.0f);

        // ---- feed-forward block ----
        ln_kernel<<<TOK,128>>>(x, ln2_g + i*DIMM, ln2_b + i*DIMM, py);

        dim3 gW1(TOK/128, FFD/128, 1);
        mma_gemm<2,0><<<gW1,256>>>(py, W1 + (size_t)i*DIMM*FFD, b1 + i*FFD, nullptr, ph,
                                   DIMM, DIMM, FFD, FFD, 0, 0, 0, 1, 0, 1.0f);
        dim3 gW2(TOK/128, DIMM/128, 1);
        mma_gemm<1,0><<<gW2,256>>>(ph, W2 + (size_t)i*FFD*DIMM, b2 + i*DIMM, x, x,
                                   FFD, FFD, DIMM, DIMM, DIMM, 0, 0, 1, 0, 1.0f);
    }
}

// round 8
// speedup vs baseline: 2.0040x; 1.1439x over previous
#include <cuda_runtime.h>
#include <math.h>

// ---------------- problem constants ----------------
#define DEPTH  2
#define NBATCH 4
#define SEQ    8192
#define DIMM   512
#define HEADS  8
#define DHEAD  64
#define NBF    256          // random features m
#define FFD    2048
#define TOK    (NBATCH*SEQ) // 32768
#define BH     (NBATCH*HEADS) // 32

#define NORMALIZER 0.3535533905932738f   // 64^-0.25
#define RATIO      0.0625f               // 256^-0.5
#define PHI_EPS    1e-4f
#define LN_EPS     1e-5f
#define RSQRT2     0.70710678118654752f

// ---------------- device scratch (allocation-free) ----------------
#define TD ((size_t)TOK*DIMM)
__device__ float g_arena[13*TD];
__device__ float g_projT[DHEAD*NBF];
__device__ float g_ksum[BH*NBF];
__device__ int   g_kmax[BH];
__device__ float g_ctx[BH*NBF*DHEAD];
__device__ float g_dinv[BH*SEQ];

// ---------------- helpers ----------------
__device__ __forceinline__ float warpSum(float v){
    #pragma unroll
    for (int o=16;o;o>>=1) v += __shfl_xor_sync(0xffffffffu, v, o);
    return v;
}
__device__ __forceinline__ float warpMax(float v){
    #pragma unroll
    for (int o=16;o;o>>=1) v = fmaxf(v, __shfl_xor_sync(0xffffffffu, v, o));
    return v;
}
__device__ __forceinline__ int   f2ord(float f){ int i=__float_as_int(f); return i ^ ((i>>31) & 0x7fffffff); }
__device__ __forceinline__ float ord2f(int i){ return __int_as_float(i ^ ((i>>31) & 0x7fffffff)); }

__device__ __forceinline__ float tf32r(float x){
    unsigned u;
    asm("cvt.rna.tf32.f32 %0, %1;" : "=r"(u) : "f"(x));
    return __uint_as_float(u);
}

__device__ __forceinline__ void mma8(float* d, const float* a, const float* b){
    asm volatile(
      "mma.sync.aligned.m16n8k8.row.col.f32.tf32.tf32.f32 "
      "{%0,%1,%2,%3},{%4,%5,%6,%7},{%8,%9},{%0,%1,%2,%3};"
      : "+f"(d[0]),"+f"(d[1]),"+f"(d[2]),"+f"(d[3])
      : "r"(__float_as_uint(a[0])),"r"(__float_as_uint(a[1])),
        "r"(__float_as_uint(a[2])),"r"(__float_as_uint(a[3])),
        "r"(__float_as_uint(b[0])),"r"(__float_as_uint(b[1])));
}

// ldmatrix x4: loads the full m16k8 tf32 A-fragment (a0..a3) in one instruction.
__device__ __forceinline__ void ldmx4(float* f, unsigned a){
    unsigned r0,r1,r2,r3;
    asm volatile("ldmatrix.sync.aligned.m8n8.x4.shared.b16 {%0,%1,%2,%3}, [%4];"
                 : "=r"(r0),"=r"(r1),"=r"(r2),"=r"(r3) : "r"(a));
    f[0]=__uint_as_float(r0); f[1]=__uint_as_float(r1);
    f[2]=__uint_as_float(r2); f[3]=__uint_as_float(r3);
}

// ---------------- layernorm: one block per token ----------------
__global__ void ln_kernel(const float* __restrict__ x, const float* __restrict__ g,
                          const float* __restrict__ b, float* __restrict__ y)
{
    int t = blockIdx.x;
    int tid = threadIdx.x;              // 128 threads, 4 floats each
    const float4* xr = (const float4*)(x + (size_t)t*DIMM);
    float4 v = xr[tid];
    __shared__ float wred[4];
    __shared__ float stats[2];
    int lane = tid & 31, w = tid >> 5;

    float s = v.x+v.y+v.z+v.w;
    s = warpSum(s);
    if (lane==0) wred[w]=s;
    __syncthreads();
    if (tid==0) stats[0] = (wred[0]+wred[1]+wred[2]+wred[3]) * (1.0f/DIMM);
    __syncthreads();
    float mean = stats[0];

    float dx0=v.x-mean, dx1=v.y-mean, dx2=v.z-mean, dx3=v.w-mean;
    float s2 = dx0*dx0+dx1*dx1+dx2*dx2+dx3*dx3;
    s2 = warpSum(s2);
    if (lane==0) wred[w]=s2;
    __syncthreads();
    if (tid==0) stats[1] = (wred[0]+wred[1]+wred[2]+wred[3]) * (1.0f/DIMM);
    __syncthreads();
    float inv = rsqrtf(stats[1] + LN_EPS);

    float4 gv = ((const float4*)g)[tid];
    float4 bv = ((const float4*)b)[tid];
    float4 out;
    out.x = dx0*inv*gv.x + bv.x;
    out.y = dx1*inv*gv.y + bv.y;
    out.z = dx2*inv*gv.z + bv.z;
    out.w = dx3*inv*gv.w + bv.w;
    ((float4*)(y + (size_t)t*DIMM))[tid] = out;
}

// ---------------- tf32 tensor-core GEMM, 128x128x16 tile ----------------
// EPI: 0 = bias, 1 = bias + residual, 2 = gelu(bias), 3 = write + block max -> g_kmax[bz]
// SPLIT: 1 = 3xTF32 (near-fp32 accuracy), 0 = single-pass tf32
#define BM 128
#define BN 128
#define BK 16
#define ASTR 20      // Ah row stride (floats): ldmatrix row-starts hit disjoint banks
#define BSTR 136     // Bh row stride (floats): conflict-free scalar fragment loads

template<int EPI, int SPLIT>
__global__ void __launch_bounds__(256)
mma_gemm(const float* __restrict__ A, const float* __restrict__ Bm,
         const float* __restrict__ bias, const float* __restrict__ R,
         float* __restrict__ C,
         int K, int lda, int ldb, int ldc, int ldr,
         long strideAb, long strideAh, int Hn, long strideC, float alpha)
{
    int bz = blockIdx.z;
    const float* Ab = A + (long)(bz / Hn)*strideAb + (long)(bz % Hn)*strideAh;
    float* Cb = C + (long)bz*strideC;
    int row0 = blockIdx.x*BM, col0 = blockIdx.y*BN;

    __shared__ float Ah[BM][ASTR];
    __shared__ float Bh[BK][BSTR];
    __shared__ float Al[SPLIT?BM:1][ASTR];
    __shared__ float Bl[SPLIT?BK:1][BSTR];
    __shared__ float rmax[8];

    int tid  = threadIdx.x;
    int lane = tid & 31;
    int warp = tid >> 5;
    int moff = (warp >> 2)*64;   // 2 warp rows
    int noff = (warp & 3)*32;    // 4 warp cols
    int t4   = lane >> 2;        // 0..7
    int tm4  = lane & 3;         // 0..3

    // ldmatrix per-thread source: grp 0..3 -> (row block, col half)
    int grp = lane >> 3, rr = lane & 7;
    int arow_ld = moff + rr + (grp & 1)*8;
    int acol_ld = (grp >> 1)*4;
    unsigned aAddr  = (unsigned)__cvta_generic_to_shared(&Ah[0][0])
                    + (unsigned)((arow_ld*ASTR + acol_ld)*4);
    unsigned alAddr = (unsigned)__cvta_generic_to_shared(&Al[0][0])
                    + (unsigned)((arow_ld*ASTR + acol_ld)*4);

    // B fragment base pointers (compile-time offsets added in the loop)
    const float* bPt  = &Bh[0][0] + tm4*BSTR + noff + t4;
    const float* blPt = &Bl[0][0] + tm4*BSTR + noff + t4;

    // global load mapping (float4 granularity)
    int a_row0 = tid >> 2,           a_c4 = (tid & 3)*4;     // + second: row+64
    int b_row0 = tid >> 5,           b_c4 = (tid & 31)*4;    // + second: row+8

    const float* aL0 = Ab + (long)(row0 + a_row0     )*lda + a_c4;
    const float* aL1 = Ab + (long)(row0 + a_row0 + 64)*lda + a_c4;
    const float* bL0 = Bm + (long)(b_row0    )*ldb + col0 + b_c4;
    const float* bL1 = Bm + (long)(b_row0 + 8)*ldb + col0 + b_c4;

    float acc[4][4][4];
    #pragma unroll
    for (int i=0;i<4;i++)
        #pragma unroll
        for (int j=0;j<4;j++)
            #pragma unroll
            for (int r=0;r<4;r++) acc[i][j][r]=0.f;

    float4 ra0 = *(const float4*)(aL0);
    float4 ra1 = *(const float4*)(aL1);
    float4 rb0 = *(const float4*)(bL0);
    float4 rb1 = *(const float4*)(bL1);

    for (int k0=0; k0<K; k0+=BK){
        // ---- store tile to SMEM (convert to tf32; split if requested) ----
        {
            float4 h0, h1;
            h0.x=tf32r(ra0.x); h0.y=tf32r(ra0.y); h0.z=tf32r(ra0.z); h0.w=tf32r(ra0.w);
            h1.x=tf32r(ra1.x); h1.y=tf32r(ra1.y); h1.z=tf32r(ra1.z); h1.w=tf32r(ra1.w);
            *(float4*)&Ah[a_row0   ][a_c4] = h0;
            *(float4*)&Ah[a_row0+64][a_c4] = h1;
            if (SPLIT){
                float4 l0, l1;
                l0.x=tf32r(ra0.x-h0.x); l0.y=tf32r(ra0.y-h0.y); l0.z=tf32r(ra0.z-h0.z); l0.w=tf32r(ra0.w-h0.w);
                l1.x=tf32r(ra1.x-h1.x); l1.y=tf32r(ra1.y-h1.y); l1.z=tf32r(ra1.z-h1.z); l1.w=tf32r(ra1.w-h1.w);
                *(float4*)&Al[a_row0   ][a_c4] = l0;
                *(float4*)&Al[a_row0+64][a_c4] = l1;
            }
            float4 g0, g1;
            g0.x=tf32r(rb0.x); g0.y=tf32r(rb0.y); g0.z=tf32r(rb0.z); g0.w=tf32r(rb0.w);
            g1.x=tf32r(rb1.x); g1.y=tf32r(rb1.y); g1.z=tf32r(rb1.z); g1.w=tf32r(rb1.w);
            *(float4*)&Bh[b_row0  ][b_c4] = g0;
            *(float4*)&Bh[b_row0+8][b_c4] = g1;
            if (SPLIT){
                float4 l0, l1;
                l0.x=tf32r(rb0.x-g0.x); l0.y=tf32r(rb0.y-g0.y); l0.z=tf32r(rb0.z-g0.z); l0.w=tf32r(rb0.w-g0.w);
                l1.x=tf32r(rb1.x-g1.x); l1.y=tf32r(rb1.y-g1.y); l1.z=tf32r(rb1.z-g1.z); l1.w=tf32r(rb1.w-g1.w);
                *(float4*)&Bl[b_row0  ][b_c4] = l0;
                *(float4*)&Bl[b_row0+8][b_c4] = l1;
            }
        }
        __syncthreads();

        // ---- prefetch next tile ----
        if (k0 + BK < K){
            ra0 = *(const float4*)(aL0 + k0 + BK);
            ra1 = *(const float4*)(aL1 + k0 + BK);
            rb0 = *(const float4*)(bL0 + (long)(k0+BK)*ldb);
            rb1 = *(const float4*)(bL1 + (long)(k0+BK)*ldb);
        }

        // ---- compute: two k8 sub-steps ----
        #pragma unroll
        for (int kk=0; kk<BK; kk+=8){
            float af[4][4], bf[4][2];
            #pragma unroll
            for (int mt=0; mt<4; mt++)
                ldmx4(af[mt], aAddr + (unsigned)((mt*16*ASTR + kk)*4));
            #pragma unroll
            for (int nt=0; nt<4; nt++){
                bf[nt][0] = bPt[(kk  )*BSTR + nt*8];
                bf[nt][1] = bPt[(kk+4)*BSTR + nt*8];
            }
            #pragma unroll
            for (int mt=0; mt<4; mt++)
                #pragma unroll
                for (int nt=0; nt<4; nt++)
                    mma8(acc[mt][nt], af[mt], bf[nt]);

            if (SPLIT){
                float al[4][4], bl[4][2];
                #pragma unroll
                for (int mt=0; mt<4; mt++)
                    ldmx4(al[mt], alAddr + (unsigned)((mt*16*ASTR + kk)*4));
                #pragma unroll
                for (int nt=0; nt<4; nt++){
                    bl[nt][0] = blPt[(kk  )*BSTR + nt*8];
                    bl[nt][1] = blPt[(kk+4)*BSTR + nt*8];
                }
                #pragma unroll
                for (int mt=0; mt<4; mt++)
                    #pragma unroll
                    for (int nt=0; nt<4; nt++){
                        mma8(acc[mt][nt], af[mt], bl[nt]);   // hi*lo
                        mma8(acc[mt][nt], al[mt], bf[nt]);   // lo*hi
                    }
            }
        }
        __syncthreads();
    }

    // ---- epilogue ----
    float vmax = -INFINITY;
    #pragma unroll
    for (int nt=0; nt<4; nt++){
        int col = col0 + noff + nt*8 + 2*tm4;
        float b0 = bias ? bias[col]   : 0.f;
        float b1 = bias ? bias[col+1] : 0.f;
        #pragma unroll
        for (int mt=0; mt<4; mt++){
            int row = row0 + moff + mt*16 + t4;
            float v0 = (acc[mt][nt][0] + b0)*alpha;
            float v1 = (acc[mt][nt][1] + b1)*alpha;
            float v2 = (acc[mt][nt][2] + b0)*alpha;
            float v3 = (acc[mt][nt][3] + b1)*alpha;
            if (EPI==2){
                v0 = 0.5f*v0*(1.0f + erff(v0*RSQRT2));
                v1 = 0.5f*v1*(1.0f + erff(v1*RSQRT2));
                v2 = 0.5f*v2*(1.0f + erff(v2*RSQRT2));
                v3 = 0.5f*v3*(1.0f + erff(v3*RSQRT2));
            }
            if (EPI==1){
                v0 += R[(long)row*ldr + col];
                v1 += R[(long)row*ldr + col+1];
                v2 += R[(long)(row+8)*ldr + col];
                v3 += R[(long)(row+8)*ldr + col+1];
            }
            if (EPI==3){
                vmax = fmaxf(vmax, fmaxf(fmaxf(v0,v1), fmaxf(v2,v3)));
            }
            float2 p0 = make_float2(v0, v1);
            float2 p1 = make_float2(v2, v3);
            *(float2*)(&Cb[(long)row*ldc + col])     = p0;
            *(float2*)(&Cb[(long)(row+8)*ldc + col]) = p1;
        }
    }
    if (EPI==3){
        float m = warpMax(vmax);
        if (lane==0) rmax[warp]=m;
        __syncthreads();
        if (tid==0){
            float t=-INFINITY;
            #pragma unroll
            for (int i=0;i<8;i++) t = fmaxf(t, rmax[i]);
            atomicMax(&g_kmax[blockIdx.z], f2ord(t));
        }
    }
}

// ---------------- proj transpose: [256,64] -> [64,256] ----------------
__global__ void transpose_proj(const float* __restrict__ proj, float* __restrict__ pt)
{
    int idx = blockIdx.x*256 + threadIdx.x;   // over 16384
    if (idx < NBF*DHEAD){
        int m = idx >> 6, k = idx & 63;
        pt[k*NBF + m] = proj[idx];
    }
}

// ---------------- zero / init per layer (must run BEFORE dash-k GEMM) ----------------
__global__ void init_kernel()
{
    int idx = blockIdx.x*256 + threadIdx.x;
    if (idx < BH*NBF*DHEAD) g_ctx[idx] = 0.f;
    if (idx < BH*NBF)       g_ksum[idx] = 0.f;
    if (idx < BH)           g_kmax[idx] = f2ord(-INFINITY);
}

// ---------------- phi finish ----------------
// QMODE=false: uses global k-max (accumulated in dash-k epilogue)
// QMODE=true : per-row max; ALSO computes d_inv (needs g_ksum ready)
template<bool QMODE>
__global__ void phi_finish(const float* __restrict__ qk, float* __restrict__ dash)
{
    int bh = blockIdx.y, n = blockIdx.x;
    int b = bh >> 3, h = bh & 7;
    int tid = threadIdx.x;     // 256 = NBF
    float* row = dash + ((size_t)bh*SEQ + n)*NBF;
    float dv = row[tid];
    const float* qrow = qk + ((size_t)(b*SEQ + n))*DIMM + h*DHEAD;
    float q2 = (tid < DHEAD) ? qrow[tid]*qrow[tid] : 0.f;

    __shared__ float wred[8];
    __shared__ float res[2];
    int lane = tid & 31, w = tid >> 5;

    float s = warpSum(q2);
    if (lane==0) wred[w]=s;
    __syncthreads();
    if (tid==0){
        float t=0.f;
        #pragma unroll
        for (int i=0;i<8;i++) t += wred[i];
        res[0]=t;
    }
    __syncthreads();

    float mx;
    if (QMODE){
        float m = warpMax(dv);
        if (lane==0) wred[w]=m;
        __syncthreads();
        if (tid==0){
            float t=-INFINITY;
            #pragma unroll
            for (int i=0;i<8;i++) t = fmaxf(t, wred[i]);
            res[1]=t;
        }
        __syncthreads();
        mx = res[1];
    } else {
        mx = ord2f(g_kmax[bh]);
    }
    float diag = 0.5f*res[0];
    float val = RATIO*(expf(dv - diag - mx) + PHI_EPS);
    row[tid] = val;

    if (QMODE){
        // fused d_inv: 1 / dot(qp_row, k_sum)
        float contrib = val * g_ksum[bh*NBF + tid];
        float s2 = warpSum(contrib);
        if (lane==0) wred[w]=s2;
        __syncthreads();
        if (tid==0){
            float t=0.f;
            #pragma unroll
            for (int i=0;i<8;i++) t += wred[i];
            g_dinv[(size_t)bh*SEQ + n] = 1.0f/t;
        }
    }
}

// ---------------- k_sum[bh][m] = sum_n kp ----------------
__global__ void ksum_kernel(const float* __restrict__ kp)
{
    int bh = blockIdx.y;
    int n0 = blockIdx.x*(SEQ/32);
    int tid = threadIdx.x;  // 256 = NBF
    const float* base = kp + ((size_t)bh*SEQ + n0)*NBF + tid;
    float s = 0.f;
    #pragma unroll 4
    for (int r=0; r<SEQ/32; r++) s += base[(size_t)r*NBF];
    atomicAdd(&g_ksum[bh*NBF + tid], s);
}

// ---------------- ctx[bh][m][d] = sum_n kp[bh][n][m]*v[b][n][h][d] (split-K + atomics) ----------------
__global__ void __launch_bounds__(256)
ctx_kernel(const float* __restrict__ kp, const float* __restrict__ v)
{
    int bh = blockIdx.z; int b = bh >> 3, h = bh & 7;
    const float* kpb = kp + (size_t)bh*SEQ*NBF;
    const float* vb  = v  + (size_t)b*SEQ*DIMM + h*DHEAD;
    int m0 = blockIdx.x*64;
    int n0 = blockIdx.y*(SEQ/8);  // 1024 per split

    __shared__ float Ks[16][64];
    __shared__ float Vs[16][64];
    int tid = threadIdx.x;
    int ty = tid >> 4, tx = tid & 15;
    int lr = tid >> 4, lc4 = (tid & 15)*4;

    float acc[4][4];
    #pragma unroll
    for (int i=0;i<4;i++)
        #pragma unroll
        for (int j=0;j<4;j++) acc[i][j]=0.f;

    for (int n=n0; n<n0+SEQ/8; n+=16){
        __syncthreads();
        *(float4*)(&Ks[lr][lc4]) = *(const float4*)(kpb + (size_t)(n+lr)*NBF + m0 + lc4);
        *(float4*)(&Vs[lr][lc4]) = *(const float4*)(vb  + (size_t)(n+lr)*DIMM + lc4);
        __syncthreads();
        #pragma unroll
        for (int kk=0;kk<16;kk++){
            float a[4], bb[4];
            #pragma unroll
            for (int i=0;i<4;i++) a[i]  = Ks[kk][ty*4+i];
            #pragma unroll
            for (int j=0;j<4;j++) bb[j] = Vs[kk][tx*4+j];
            #pragma unroll
            for (int i=0;i<4;i++)
                #pragma unroll
                for (int j=0;j<4;j++) acc[i][j] = fmaf(a[i], bb[j], acc[i][j]);
        }
    }
    #pragma unroll
    for (int i=0;i<4;i++)
        #pragma unroll
        for (int j=0;j<4;j++)
            atomicAdd(&g_ctx[((size_t)bh*NBF + m0 + ty*4 + i)*DHEAD + tx*4 + j], acc[i][j]);
}

// ---------------- o = dinv * (qp @ ctx), scattered into [T, 512] ----------------
__global__ void __launch_bounds__(256, 2)
ogemm_kernel(const float* __restrict__ qp, float* __restrict__ o)
{
    int bh = blockIdx.z; int b = bh >> 3, h = bh & 7;
    const float* A  = qp    + (size_t)bh*SEQ*NBF;
    const float* Bm = g_ctx + (size_t)bh*NBF*DHEAD;
    int row0 = blockIdx.x*128;

    __shared__ float As[8][128];
    __shared__ float Bs[8][64];
    int tid = threadIdx.x;
    int ty = tid >> 4, tx = tid & 15;

    float acc[8][4];
    #pragma unroll
    for (int i=0;i<8;i++)
        #pragma unroll
        for (int j=0;j<4;j++) acc[i][j]=0.f;

    for (int k0=0; k0<NBF; k0+=8){
        float4 av = *(const float4*)(A + (size_t)(row0 + (tid>>1))*NBF + k0 + (tid&1)*4);
        __syncthreads();
        {
            int arow = tid >> 1, acol4 = (tid & 1)*4;
            As[acol4+0][arow]=av.x; As[acol4+1][arow]=av.y;
            As[acol4+2][arow]=av.z; As[acol4+3][arow]=av.w;
        }
        if (tid < 128)
            *(float4*)(&Bs[tid>>4][(tid&15)*4]) =
                *(const float4*)(Bm + (size_t)(k0 + (tid>>4))*DHEAD + (tid&15)*4);
        __syncthreads();
        #pragma unroll
        for (int kk=0;kk<8;kk++){
            float a[8], bb[4];
            #pragma unroll
            for (int i=0;i<8;i++) a[i]  = As[kk][ty*8+i];
            #pragma unroll
            for (int j=0;j<4;j++) bb[j] = Bs[kk][tx*4+j];
            #pragma unroll
            for (int i=0;i<8;i++)
                #pragma unroll
                for (int j=0;j<4;j++) acc[i][j] = fmaf(a[i], bb[j], acc[i][j]);
        }
    }
    #pragma unroll
    for (int i=0;i<8;i++){
        int n = row0 + ty*8 + i;
        float di = g_dinv[(size_t)bh*SEQ + n];
        #pragma unroll
        for (int j=0;j<4;j++)
            o[((size_t)(b*SEQ + n))*DIMM + h*DHEAD + tx*4 + j] = acc[i][j]*di;
    }
}

// ---------------- host driver ----------------
extern "C" void kernel_launch(void* const* d_in, const int* in_sizes, int n_in,
                              void* d_out, int out_size)
{
    const float* ln1_g = (const float*)d_in[1];
    const float* ln1_b = (const float*)d_in[2];
    const float* ln2_g = (const float*)d_in[3];
    const float* ln2_b = (const float*)d_in[4];
    const float* Wq    = (const float*)d_in[5];
    const float* bq    = (const float*)d_in[6];
    const float* Wk    = (const float*)d_in[7];
    const float* bk    = (const float*)d_in[8];
    const float* Wv    = (const float*)d_in[9];
    const float* bv    = (const float*)d_in[10];
    const float* Wo    = (const float*)d_in[11];
    const float* bo    = (const float*)d_in[12];
    const float* proj  = (const float*)d_in[13];
    const float* W1    = (const float*)d_in[14];
    const float* b1    = (const float*)d_in[15];
    const float* W2    = (const float*)d_in[16];
    const float* b2    = (const float*)d_in[17];

    float* x = (float*)d_out;
    cudaMemcpyAsync(x, d_in[0], TD*sizeof(float), cudaMemcpyDeviceToDevice);

    float* arena;
    cudaGetSymbolAddress((void**)&arena, g_arena);
    float* py  = arena;            // TD
    float* pq  = arena + TD;       // TD
    float* pk  = arena + 2*TD;     // TD
    float* pv  = arena + 3*TD;     // TD
    float* po  = arena + 4*TD;     // TD
    float* ph  = arena + TD;       // 4*TD, aliases q..o (FF phase only)
    float* pqp = arena + 5*TD;     // 4*TD
    float* pkp = arena + 9*TD;     // 4*TD
    float* pprojT;
    cudaGetSymbolAddress((void**)&pprojT, g_projT);

    for (int i=0; i<DEPTH; i++){
        // ---- attention block ----
        ln_kernel<<<TOK,128>>>(x, ln1_g + i*DIMM, ln1_b + i*DIMM, py);

        dim3 gQKV(TOK/128, DIMM/128, 1);
        // all single-pass tf32: averaging through ctx/o and the residual scale
        // keep the final error well under the 1e-3 threshold
        mma_gemm<0,0><<<gQKV,256>>>(py, Wq + (size_t)i*DIMM*DIMM, bq + i*DIMM, nullptr, pq,
                                    DIMM, DIMM, DIMM, DIMM, 0, 0, 0, 1, 0, NORMALIZER);
        mma_gemm<0,0><<<gQKV,256>>>(py, Wk + (size_t)i*DIMM*DIMM, bk + i*DIMM, nullptr, pk,
                                    DIMM, DIMM, DIMM, DIMM, 0, 0, 0, 1, 0, NORMALIZER);
        mma_gemm<0,0><<<gQKV,256>>>(py, Wv + (size_t)i*DIMM*DIMM, bv + i*DIMM, nullptr, pv,
                                    DIMM, DIMM, DIMM, DIMM, 0, 0, 0, 1, 0, 1.0f);

        transpose_proj<<<64,256>>>(proj + (size_t)i*NBF*DHEAD, pprojT);
        init_kernel<<<2048,256>>>();   // resets ctx/ksum/kmax BEFORE dash-k (kmax fused there)

        // kdash = k_head @ projT  (batched over (b,h)); EPI=3 fuses global k-max
        dim3 gDASH(SEQ/128, NBF/128, BH);
        mma_gemm<3,0><<<gDASH,256>>>(pk, pprojT, nullptr, nullptr, pkp,
                                     DHEAD, DIMM, NBF, NBF, 0,
                                     (long)SEQ*DIMM, DHEAD, HEADS, (long)SEQ*NBF, 1.0f);
        phi_finish<false><<<dim3(SEQ,BH),256>>>(pk, pkp);
        ksum_kernel<<<dim3(32,BH),256>>>(pkp);

        // qdash = q_head @ projT, then per-row finish (+ fused d_inv; needs ksum)
        mma_gemm<0,0><<<gDASH,256>>>(pq, pprojT, nullptr, nullptr, pqp,
                                     DHEAD, DIMM, NBF, NBF, 0,
                                     (long)SEQ*DIMM, DHEAD, HEADS, (long)SEQ*NBF, 1.0f);
        phi_finish<true><<<dim3(SEQ,BH),256>>>(pq, pqp);

        ctx_kernel<<<dim3(NBF/64, 8, BH),256>>>(pkp, pv);
        ogemm_kernel<<<dim3(SEQ/128, 1, BH),256>>>(pqp, po);

        // x += o @ Wo + bo
        mma_gemm<1,0><<<gQKV,256>>>(po, Wo + (size_t)i*DIMM*DIMM, bo + i*DIMM, x, x,
                                    DIMM, DIMM, DIMM, DIMM, DIMM, 0, 0, 1, 0, 1.0f);

        // ---- feed-forward block ----
        ln_kernel<<<TOK,128>>>(x, ln2_g + i*DIMM, ln2_b + i*DIMM, py);

        dim3 gW1(TOK/128, FFD/128, 1);
        mma_gemm<2,0><<<gW1,256>>>(py, W1 + (size_t)i*DIMM*FFD, b1 + i*FFD, nullptr, ph,
                                   DIMM, DIMM, FFD, FFD, 0, 0, 0, 1, 0, 1.0f);
        dim3 gW2(TOK/128, DIMM/128, 1);
        mma_gemm<1,0><<<gW2,256>>>(ph, W2 + (size_t)i*FFD*DIMM, b2 + i*DIMM, x, x,
                                   FFD, FFD, DIMM, DIMM, DIMM, 0, 0, 1, 0, 1.0f);
    }
}